// round 1
// baseline (speedup 1.0000x reference)
#include <cuda_runtime.h>
#include <math.h>

#define PAIRS 8
#define CC 128
#define NN 4096
#define TN 64
#define TM 64
#define VS 132   // V smem row stride: 128 desc + x + y + w + pad
#define PS 68    // P smem row stride (padded)
#define NTHR 256

// Scratch for pre-normalized descriptors (x10 folded in so S = 100*cos)
__device__ float g_qn[PAIRS * CC * NN];
__device__ float g_kn[PAIRS * CC * NN];

__global__ void normalize_kernel(const float* __restrict__ desc) {
    int idx = blockIdx.x * blockDim.x + threadIdx.x;   // 0 .. 16*4096-1
    int b = idx >> 12;
    int n = idx & (NN - 1);
    const float* col = desc + (size_t)b * CC * NN + n;
    float ss = 0.f;
#pragma unroll 8
    for (int c = 0; c < CC; c++) { float v = col[(size_t)c * NN]; ss = fmaf(v, v, ss); }
    float inv = 10.f / fmaxf(sqrtf(ss), 1e-12f);
    float* dst = ((b & 1) ? g_kn : g_qn) + (size_t)(b >> 1) * CC * NN + n;
#pragma unroll 8
    for (int c = 0; c < CC; c++) dst[(size_t)c * NN] = col[(size_t)c * NN] * inv;
}

__global__ void __launch_bounds__(NTHR, 1)
flash_kernel(const float* __restrict__ coords,
             const float* __restrict__ weights,
             const float* __restrict__ desc,
             float* __restrict__ out)
{
    extern __shared__ float sm[];
    float* qs = sm;                    // [CC][TN]
    float* ks = qs + CC * TN;          // [CC][TM]
    float* vs = ks + CC * TM;          // [TM][VS]
    float* ps = vs + TM * VS;          // [TN][PS]

    int p  = blockIdx.y;
    int n0 = blockIdx.x * TN;
    int tid = threadIdx.x;
    int tx = tid & 15;                 // 16 groups along m (GEMM1) / v-cols (GEMM2)
    int ty = tid >> 4;                 // 16 groups along n, 4 rows each

    const float* qsrc     = g_qn + (size_t)p * CC * NN;
    const float* ksrc     = g_kn + (size_t)p * CC * NN;
    const float* vdesc    = desc    + (size_t)(2 * p + 1) * CC * NN;
    const float* tcoords  = coords  + (size_t)(2 * p + 1) * 2 * NN;
    const float* tweights = weights + (size_t)(2 * p + 1) * NN;

    // Load Q tile (stays resident)
    for (int i = tid; i < CC * TN / 4; i += NTHR) {
        int c = i >> 4, nv = i & 15;
        *(float4*)(qs + c * TN + nv * 4) =
            *(const float4*)(qsrc + (size_t)c * NN + n0 + nv * 4);
    }

    float m_r[4], l_r[4], acc[4][8], acc_e[4];
#pragma unroll
    for (int r = 0; r < 4; r++) {
        m_r[r] = -1e30f; l_r[r] = 0.f; acc_e[r] = 0.f;
#pragma unroll
        for (int v = 0; v < 8; v++) acc[r][v] = 0.f;
    }

    for (int mt = 0; mt < NN / TM; ++mt) {
        int m0 = mt * TM;
        __syncthreads();   // previous iteration fully done with ks/vs/ps

        // K tile
        for (int i = tid; i < CC * TM / 4; i += NTHR) {
            int c = i >> 4, mv = i & 15;
            *(float4*)(ks + c * TM + mv * 4) =
                *(const float4*)(ksrc + (size_t)c * NN + m0 + mv * 4);
        }
        // V tile: raw tgt_desc, transposed into [m][c]
        for (int i = tid; i < CC * TM / 4; i += NTHR) {
            int c = i >> 4, mv = i & 15;
            float4 g = *(const float4*)(vdesc + (size_t)c * NN + m0 + mv * 4);
            vs[(mv * 4 + 0) * VS + c] = g.x;
            vs[(mv * 4 + 1) * VS + c] = g.y;
            vs[(mv * 4 + 2) * VS + c] = g.z;
            vs[(mv * 4 + 3) * VS + c] = g.w;
        }
        if (tid < TM) {
            vs[tid * VS + 128] = tcoords[m0 + tid];
            vs[tid * VS + 129] = tcoords[NN + m0 + tid];
            vs[tid * VS + 130] = tweights[m0 + tid];
            vs[tid * VS + 131] = 0.f;
        }
        __syncthreads();

        // ---- GEMM1: S[4x4] = Q^T K over C=128 ----
        float s[4][4];
#pragma unroll
        for (int r = 0; r < 4; r++)
#pragma unroll
            for (int j = 0; j < 4; j++) s[r][j] = 0.f;

#pragma unroll 8
        for (int c = 0; c < CC; c++) {
            float4 qv = *(float4*)(qs + c * TN + ty * 4);
            float4 kv = *(float4*)(ks + c * TM + tx * 4);
            float qa[4] = {qv.x, qv.y, qv.z, qv.w};
            float ka[4] = {kv.x, kv.y, kv.z, kv.w};
#pragma unroll
            for (int r = 0; r < 4; r++)
#pragma unroll
                for (int j = 0; j < 4; j++)
                    s[r][j] = fmaf(qa[r], ka[j], s[r][j]);
        }

        // ---- online softmax (rows replicated across the 16 tx lanes) ----
#pragma unroll
        for (int r = 0; r < 4; r++) {
            float tmax = fmaxf(fmaxf(s[r][0], s[r][1]), fmaxf(s[r][2], s[r][3]));
#pragma unroll
            for (int off = 8; off; off >>= 1)
                tmax = fmaxf(tmax, __shfl_xor_sync(0xffffffffu, tmax, off, 16));
            float mn = fmaxf(m_r[r], tmax);
            float corr = __expf(m_r[r] - mn);
            m_r[r] = mn;
            float psum = 0.f;
#pragma unroll
            for (int j = 0; j < 4; j++) { s[r][j] = __expf(s[r][j] - mn); psum += s[r][j]; }
#pragma unroll
            for (int off = 8; off; off >>= 1)
                psum += __shfl_xor_sync(0xffffffffu, psum, off, 16);
            l_r[r] = l_r[r] * corr + psum;
#pragma unroll
            for (int v = 0; v < 8; v++) acc[r][v] *= corr;
            acc_e[r] *= corr;
            *(float4*)(ps + (ty * 4 + r) * PS + tx * 4) =
                make_float4(s[r][0], s[r][1], s[r][2], s[r][3]);
        }
        __syncwarp();   // P rows of this ty-group written only by this warp

        // ---- GEMM2: acc += P * V ----
#pragma unroll 4
        for (int j = 0; j < TM; j++) {
            float4 va = *(float4*)(vs + j * VS + tx * 8);
            float4 vb = *(float4*)(vs + j * VS + tx * 8 + 4);
            float ve = (tx < 3) ? vs[j * VS + 128 + tx] : 0.f;
            float vv[8] = {va.x, va.y, va.z, va.w, vb.x, vb.y, vb.z, vb.w};
#pragma unroll
            for (int r = 0; r < 4; r++) {
                float pj = ps[(ty * 4 + r) * PS + j];
#pragma unroll
                for (int v = 0; v < 8; v++) acc[r][v] = fmaf(pj, vv[v], acc[r][v]);
                acc_e[r] = fmaf(pj, ve, acc_e[r]);
            }
        }
    }

    // ---- epilogue ----
    // pseudo_desc normalization: acc/l normalized over c == acc normalized over c
    const float* sdesc    = desc    + (size_t)(2 * p) * CC * NN;   // raw src desc
    const float* sweights = weights + (size_t)(2 * p) * NN;
    float* out_c = out + (size_t)p * 2 * NN;
    float* out_w = out + (size_t)PAIRS * 2 * NN + (size_t)p * NN;

#pragma unroll
    for (int r = 0; r < 4; r++) {
        int n = n0 + ty * 4 + r;
        float ss = 0.f, dot = 0.f;
#pragma unroll
        for (int v = 0; v < 8; v++) {
            int c = tx * 8 + v;
            float a = acc[r][v];
            ss  = fmaf(a, a, ss);
            dot = fmaf(a, sdesc[(size_t)c * NN + n], dot);
        }
#pragma unroll
        for (int off = 8; off; off >>= 1) {
            ss  += __shfl_xor_sync(0xffffffffu, ss, off, 16);
            dot += __shfl_xor_sync(0xffffffffu, dot, off, 16);
        }
        float linv = 1.f / l_r[r];
        if (tx == 0) {
            out_c[n] = acc_e[r] * linv;                        // pseudo x
        } else if (tx == 1) {
            out_c[NN + n] = acc_e[r] * linv;                   // pseudo y
        } else if (tx == 2) {
            float pw = acc_e[r] * linv;                        // pseudo weight
            float score = dot / (fmaxf(sqrtf(ss), 1e-12f) * 128.f);
            out_w[n] = 0.5f * (score + 1.f) * sweights[n] * pw;
        }
    }
}

extern "C" void kernel_launch(void* const* d_in, const int* in_sizes, int n_in,
                              void* d_out, int out_size) {
    const float* coords  = (const float*)d_in[0];  // [16][2][4096]
    const float* weights = (const float*)d_in[1];  // [16][1][4096]
    const float* desc    = (const float*)d_in[2];  // [16][128][4096]
    float* out = (float*)d_out;                    // 65536 coords + 32768 weights

    size_t smem = (size_t)(CC * TN + CC * TM + TM * VS + TN * PS) * sizeof(float);
    cudaFuncSetAttribute(flash_kernel,
                         cudaFuncAttributeMaxDynamicSharedMemorySize, (int)smem);

    normalize_kernel<<<(16 * NN) / 256, 256>>>(desc);
    dim3 grid(NN / TN, PAIRS);
    flash_kernel<<<grid, NTHR, smem>>>(coords, weights, desc, out);
}

// round 4
// speedup vs baseline: 1.0060x; 1.0060x over previous
#include <cuda_runtime.h>
#include <math.h>

#define PAIRS 8
#define CC 128
#define NN 4096
#define TN 64
#define TM 64
#define VS 132   // V smem row stride: 128 desc + x + y + w + pad
#define PS 68    // P smem row stride (padded)
#define NTHR 256

// Scratch for pre-normalized descriptors (x10 folded in so S = 100*cos)
__device__ float g_qn[PAIRS * CC * NN];
__device__ float g_kn[PAIRS * CC * NN];

__global__ void normalize_kernel(const float* __restrict__ desc) {
    int idx = blockIdx.x * blockDim.x + threadIdx.x;   // 0 .. 16*4096-1
    int b = idx >> 12;
    int n = idx & (NN - 1);
    const float* col = desc + (size_t)b * CC * NN + n;
    float ss = 0.f;
#pragma unroll 8
    for (int c = 0; c < CC; c++) { float v = col[(size_t)c * NN]; ss = fmaf(v, v, ss); }
    float inv = 10.f / fmaxf(sqrtf(ss), 1e-12f);
    float* dst = ((b & 1) ? g_kn : g_qn) + (size_t)(b >> 1) * CC * NN + n;
#pragma unroll 8
    for (int c = 0; c < CC; c++) dst[(size_t)c * NN] = col[(size_t)c * NN] * inv;
}

__global__ void __launch_bounds__(NTHR, 1)
flash_kernel(const float* __restrict__ coords,
             const float* __restrict__ weights,
             const float* __restrict__ desc,
             float* __restrict__ out)
{
    extern __shared__ float sm[];
    float* qs = sm;                    // [CC][TN]
    float* ks = qs + CC * TN;          // [CC][TM]
    float* vs = ks + CC * TM;          // [TM][VS]
    float* ps = vs + TM * VS;          // [TN][PS]

    int p  = blockIdx.y;
    int n0 = blockIdx.x * TN;
    int tid = threadIdx.x;
    int tx = tid & 15;                 // 16 groups along m (GEMM1) / v-cols (GEMM2)
    int ty = tid >> 4;                 // 16 groups along n, 4 rows each

    const float* qsrc     = g_qn + (size_t)p * CC * NN;
    const float* ksrc     = g_kn + (size_t)p * CC * NN;
    const float* vdesc    = desc    + (size_t)(2 * p + 1) * CC * NN;
    const float* tcoords  = coords  + (size_t)(2 * p + 1) * 2 * NN;
    const float* tweights = weights + (size_t)(2 * p + 1) * NN;

    // Load Q tile (stays resident)
    for (int i = tid; i < CC * TN / 4; i += NTHR) {
        int c = i >> 4, nv = i & 15;
        *(float4*)(qs + c * TN + nv * 4) =
            *(const float4*)(qsrc + (size_t)c * NN + n0 + nv * 4);
    }

    float m_r[4], l_r[4], acc[4][8], acc_e[4];
#pragma unroll
    for (int r = 0; r < 4; r++) {
        m_r[r] = -1e30f; l_r[r] = 0.f; acc_e[r] = 0.f;
#pragma unroll
        for (int v = 0; v < 8; v++) acc[r][v] = 0.f;
    }

    for (int mt = 0; mt < NN / TM; ++mt) {
        int m0 = mt * TM;
        __syncthreads();   // previous iteration fully done with ks/vs/ps

        // K tile
        for (int i = tid; i < CC * TM / 4; i += NTHR) {
            int c = i >> 4, mv = i & 15;
            *(float4*)(ks + c * TM + mv * 4) =
                *(const float4*)(ksrc + (size_t)c * NN + m0 + mv * 4);
        }
        // V tile: raw tgt_desc, transposed into [m][c]
        for (int i = tid; i < CC * TM / 4; i += NTHR) {
            int c = i >> 4, mv = i & 15;
            float4 g = *(const float4*)(vdesc + (size_t)c * NN + m0 + mv * 4);
            vs[(mv * 4 + 0) * VS + c] = g.x;
            vs[(mv * 4 + 1) * VS + c] = g.y;
            vs[(mv * 4 + 2) * VS + c] = g.z;
            vs[(mv * 4 + 3) * VS + c] = g.w;
        }
        if (tid < TM) {
            vs[tid * VS + 128] = tcoords[m0 + tid];
            vs[tid * VS + 129] = tcoords[NN + m0 + tid];
            vs[tid * VS + 130] = tweights[m0 + tid];
            vs[tid * VS + 131] = 0.f;
        }
        __syncthreads();

        // ---- GEMM1: S[4x4] = Q^T K over C=128 ----
        float s[4][4];
#pragma unroll
        for (int r = 0; r < 4; r++)
#pragma unroll
            for (int j = 0; j < 4; j++) s[r][j] = 0.f;

#pragma unroll 8
        for (int c = 0; c < CC; c++) {
            float4 qv = *(float4*)(qs + c * TN + ty * 4);
            float4 kv = *(float4*)(ks + c * TM + tx * 4);
            float qa[4] = {qv.x, qv.y, qv.z, qv.w};
            float ka[4] = {kv.x, kv.y, kv.z, kv.w};
#pragma unroll
            for (int r = 0; r < 4; r++)
#pragma unroll
                for (int j = 0; j < 4; j++)
                    s[r][j] = fmaf(qa[r], ka[j], s[r][j]);
        }

        // ---- online softmax (rows replicated across the 16 tx lanes) ----
#pragma unroll
        for (int r = 0; r < 4; r++) {
            float tmax = fmaxf(fmaxf(s[r][0], s[r][1]), fmaxf(s[r][2], s[r][3]));
#pragma unroll
            for (int off = 8; off; off >>= 1)
                tmax = fmaxf(tmax, __shfl_xor_sync(0xffffffffu, tmax, off, 16));
            float mn = fmaxf(m_r[r], tmax);
            float corr = __expf(m_r[r] - mn);
            m_r[r] = mn;
            float psum = 0.f;
#pragma unroll
            for (int j = 0; j < 4; j++) { s[r][j] = __expf(s[r][j] - mn); psum += s[r][j]; }
#pragma unroll
            for (int off = 8; off; off >>= 1)
                psum += __shfl_xor_sync(0xffffffffu, psum, off, 16);
            l_r[r] = l_r[r] * corr + psum;
#pragma unroll
            for (int v = 0; v < 8; v++) acc[r][v] *= corr;
            acc_e[r] *= corr;
            *(float4*)(ps + (ty * 4 + r) * PS + tx * 4) =
                make_float4(s[r][0], s[r][1], s[r][2], s[r][3]);
        }
        __syncwarp();   // P rows of this ty-group written only by this warp

        // ---- GEMM2: acc += P * V ----
#pragma unroll 4
        for (int j = 0; j < TM; j++) {
            float4 va = *(float4*)(vs + j * VS + tx * 8);
            float4 vb = *(float4*)(vs + j * VS + tx * 8 + 4);
            float ve = (tx < 3) ? vs[j * VS + 128 + tx] : 0.f;
            float vv[8] = {va.x, va.y, va.z, va.w, vb.x, vb.y, vb.z, vb.w};
#pragma unroll
            for (int r = 0; r < 4; r++) {
                float pj = ps[(ty * 4 + r) * PS + j];
#pragma unroll
                for (int v = 0; v < 8; v++) acc[r][v] = fmaf(pj, vv[v], acc[r][v]);
                acc_e[r] = fmaf(pj, ve, acc_e[r]);
            }
        }
    }

    // ---- epilogue ----
    // pseudo_desc normalization: acc/l normalized over c == acc normalized over c
    const float* sdesc    = desc    + (size_t)(2 * p) * CC * NN;   // raw src desc
    const float* sweights = weights + (size_t)(2 * p) * NN;
    float* out_c = out + (size_t)p * 2 * NN;
    float* out_w = out + (size_t)PAIRS * 2 * NN + (size_t)p * NN;

#pragma unroll
    for (int r = 0; r < 4; r++) {
        int n = n0 + ty * 4 + r;
        float ss = 0.f, dot = 0.f;
#pragma unroll
        for (int v = 0; v < 8; v++) {
            int c = tx * 8 + v;
            float a = acc[r][v];
            ss  = fmaf(a, a, ss);
            dot = fmaf(a, sdesc[(size_t)c * NN + n], dot);
        }
#pragma unroll
        for (int off = 8; off; off >>= 1) {
            ss  += __shfl_xor_sync(0xffffffffu, ss, off, 16);
            dot += __shfl_xor_sync(0xffffffffu, dot, off, 16);
        }
        float linv = 1.f / l_r[r];
        if (tx == 0) {
            out_c[n] = acc_e[r] * linv;                        // pseudo x
        } else if (tx == 1) {
            out_c[NN + n] = acc_e[r] * linv;                   // pseudo y
        } else if (tx == 2) {
            float pw = acc_e[r] * linv;                        // pseudo weight
            float score = dot / (fmaxf(sqrtf(ss), 1e-12f) * 128.f);
            out_w[n] = 0.5f * (score + 1.f) * sweights[n] * pw;
        }
    }
}

extern "C" void kernel_launch(void* const* d_in, const int* in_sizes, int n_in,
                              void* d_out, int out_size) {
    const float* coords  = (const float*)d_in[0];  // [16][2][4096]
    const float* weights = (const float*)d_in[1];  // [16][1][4096]
    const float* desc    = (const float*)d_in[2];  // [16][128][4096]
    float* out = (float*)d_out;                    // 65536 coords + 32768 weights

    size_t smem = (size_t)(CC * TN + CC * TM + TM * VS + TN * PS) * sizeof(float);
    cudaFuncSetAttribute(flash_kernel,
                         cudaFuncAttributeMaxDynamicSharedMemorySize, (int)smem);

    normalize_kernel<<<(16 * NN) / 256, 256>>>(desc);
    dim3 grid(NN / TN, PAIRS);
    flash_kernel<<<grid, NTHR, smem>>>(coords, weights, desc, out);
}

// round 5
// speedup vs baseline: 1.0674x; 1.0610x over previous
#include <cuda_runtime.h>
#include <math.h>

#define PAIRS 8
#define CC 128
#define NN 4096
#define TN 64
#define TM 64
#define VS 132   // V smem row stride: 128 desc + x + y + w + pad
#define NTHR 256

// Scratch for pre-normalized descriptors (x10 folded in so S = 100*cos)
__device__ float g_qn[PAIRS * CC * NN];
__device__ float g_kn[PAIRS * CC * NN];

__global__ void normalize_kernel(const float* __restrict__ desc) {
    int idx = blockIdx.x * blockDim.x + threadIdx.x;   // 0 .. 16*4096-1
    int b = idx >> 12;
    int n = idx & (NN - 1);
    const float* col = desc + (size_t)b * CC * NN + n;
    float ss = 0.f;
#pragma unroll 8
    for (int c = 0; c < CC; c++) { float v = col[(size_t)c * NN]; ss = fmaf(v, v, ss); }
    float inv = 10.f / fmaxf(sqrtf(ss), 1e-12f);
    float* dst = ((b & 1) ? g_kn : g_qn) + (size_t)(b >> 1) * CC * NN + n;
#pragma unroll 8
    for (int c = 0; c < CC; c++) dst[(size_t)c * NN] = col[(size_t)c * NN] * inv;
}

__global__ void __launch_bounds__(NTHR, 2)
flash_kernel(const float* __restrict__ coords,
             const float* __restrict__ weights,
             const float* __restrict__ desc,
             float* __restrict__ out)
{
    extern __shared__ float sm[];
    float* qs = sm;                    // [CC][TN]
    float* ks = qs + CC * TN;          // [CC][TM]
    float* vs = ks + CC * TM;          // [TM][VS]

    int p  = blockIdx.y;
    int n0 = blockIdx.x * TN;
    int tid = threadIdx.x;
    int tx = tid & 15;                 // 16 groups along m (GEMM1) / v-cols (GEMM2)
    int ty = tid >> 4;                 // 16 groups along n, 4 rows each

    const float* qsrc     = g_qn + (size_t)p * CC * NN;
    const float* ksrc     = g_kn + (size_t)p * CC * NN;
    const float* vdesc    = desc    + (size_t)(2 * p + 1) * CC * NN;
    const float* tcoords  = coords  + (size_t)(2 * p + 1) * 2 * NN;
    const float* tweights = weights + (size_t)(2 * p + 1) * NN;

    // Load Q tile (stays resident)
    for (int i = tid; i < CC * TN / 4; i += NTHR) {
        int c = i >> 4, nv = i & 15;
        *(float4*)(qs + c * TN + nv * 4) =
            *(const float4*)(qsrc + (size_t)c * NN + n0 + nv * 4);
    }

    float m_r[4], l_r[4], acc[4][8], acc_e[4];
#pragma unroll
    for (int r = 0; r < 4; r++) {
        m_r[r] = -1e30f; l_r[r] = 0.f; acc_e[r] = 0.f;
#pragma unroll
        for (int v = 0; v < 8; v++) acc[r][v] = 0.f;
    }

    for (int mt = 0; mt < NN / TM; ++mt) {
        int m0 = mt * TM;
        __syncthreads();   // previous iteration fully done with ks/vs

        // K tile
        for (int i = tid; i < CC * TM / 4; i += NTHR) {
            int c = i >> 4, mv = i & 15;
            *(float4*)(ks + c * TM + mv * 4) =
                *(const float4*)(ksrc + (size_t)c * NN + m0 + mv * 4);
        }
        // V tile: raw tgt_desc, transposed into [m][c]
        for (int i = tid; i < CC * TM / 4; i += NTHR) {
            int c = i >> 4, mv = i & 15;
            float4 g = *(const float4*)(vdesc + (size_t)c * NN + m0 + mv * 4);
            vs[(mv * 4 + 0) * VS + c] = g.x;
            vs[(mv * 4 + 1) * VS + c] = g.y;
            vs[(mv * 4 + 2) * VS + c] = g.z;
            vs[(mv * 4 + 3) * VS + c] = g.w;
        }
        if (tid < TM) {
            vs[tid * VS + 128] = tcoords[m0 + tid];
            vs[tid * VS + 129] = tcoords[NN + m0 + tid];
            vs[tid * VS + 130] = tweights[m0 + tid];
            vs[tid * VS + 131] = 0.f;
        }
        __syncthreads();

        // ---- GEMM1: S[4x4] = Q^T K over C=128 ----
        float s[4][4];
#pragma unroll
        for (int r = 0; r < 4; r++)
#pragma unroll
            for (int j = 0; j < 4; j++) s[r][j] = 0.f;

#pragma unroll 8
        for (int c = 0; c < CC; c++) {
            float4 qv = *(float4*)(qs + c * TN + ty * 4);
            float4 kv = *(float4*)(ks + c * TM + tx * 4);
            float qa[4] = {qv.x, qv.y, qv.z, qv.w};
            float ka[4] = {kv.x, kv.y, kv.z, kv.w};
#pragma unroll
            for (int r = 0; r < 4; r++)
#pragma unroll
                for (int j = 0; j < 4; j++)
                    s[r][j] = fmaf(qa[r], ka[j], s[r][j]);
        }

        // ---- online softmax (rows replicated across the 16 tx lanes) ----
#pragma unroll
        for (int r = 0; r < 4; r++) {
            float tmax = fmaxf(fmaxf(s[r][0], s[r][1]), fmaxf(s[r][2], s[r][3]));
#pragma unroll
            for (int off = 8; off; off >>= 1)
                tmax = fmaxf(tmax, __shfl_xor_sync(0xffffffffu, tmax, off, 16));
            float mn = fmaxf(m_r[r], tmax);
            float corr = __expf(m_r[r] - mn);
            m_r[r] = mn;
            float psum = 0.f;
#pragma unroll
            for (int j = 0; j < 4; j++) { s[r][j] = __expf(s[r][j] - mn); psum += s[r][j]; }
#pragma unroll
            for (int off = 8; off; off >>= 1)
                psum += __shfl_xor_sync(0xffffffffu, psum, off, 16);
            l_r[r] = l_r[r] * corr + psum;
#pragma unroll
            for (int v = 0; v < 8; v++) acc[r][v] *= corr;
            acc_e[r] *= corr;
        }

        // ---- GEMM2: acc += P * V, P distributed via shuffles ----
        // Lane u of each 16-lane tx group owns P columns m = u*4 .. u*4+3.
#pragma unroll 2
        for (int u = 0; u < 16; u++) {
#pragma unroll
            for (int jj = 0; jj < 4; jj++) {
                int m = u * 4 + jj;
                float4 va = *(float4*)(vs + m * VS + tx * 8);
                float4 vb = *(float4*)(vs + m * VS + tx * 8 + 4);
                float ve = (tx < 3) ? vs[m * VS + 128 + tx] : 0.f;
                float vv[8] = {va.x, va.y, va.z, va.w, vb.x, vb.y, vb.z, vb.w};
                float pr[4];
                pr[0] = __shfl_sync(0xffffffffu, s[0][jj], u, 16);
                pr[1] = __shfl_sync(0xffffffffu, s[1][jj], u, 16);
                pr[2] = __shfl_sync(0xffffffffu, s[2][jj], u, 16);
                pr[3] = __shfl_sync(0xffffffffu, s[3][jj], u, 16);
#pragma unroll
                for (int r = 0; r < 4; r++) {
#pragma unroll
                    for (int v = 0; v < 8; v++)
                        acc[r][v] = fmaf(pr[r], vv[v], acc[r][v]);
                    acc_e[r] = fmaf(pr[r], ve, acc_e[r]);
                }
            }
        }
    }

    // ---- epilogue ----
    // pseudo_desc normalization: acc/l normalized over c == acc normalized over c
    const float* sdesc    = desc    + (size_t)(2 * p) * CC * NN;   // raw src desc
    const float* sweights = weights + (size_t)(2 * p) * NN;
    float* out_c = out + (size_t)p * 2 * NN;
    float* out_w = out + (size_t)PAIRS * 2 * NN + (size_t)p * NN;

#pragma unroll
    for (int r = 0; r < 4; r++) {
        int n = n0 + ty * 4 + r;
        float ss = 0.f, dot = 0.f;
#pragma unroll
        for (int v = 0; v < 8; v++) {
            int c = tx * 8 + v;
            float a = acc[r][v];
            ss  = fmaf(a, a, ss);
            dot = fmaf(a, sdesc[(size_t)c * NN + n], dot);
        }
#pragma unroll
        for (int off = 8; off; off >>= 1) {
            ss  += __shfl_xor_sync(0xffffffffu, ss, off, 16);
            dot += __shfl_xor_sync(0xffffffffu, dot, off, 16);
        }
        float linv = 1.f / l_r[r];
        if (tx == 0) {
            out_c[n] = acc_e[r] * linv;                        // pseudo x
        } else if (tx == 1) {
            out_c[NN + n] = acc_e[r] * linv;                   // pseudo y
        } else if (tx == 2) {
            float pw = acc_e[r] * linv;                        // pseudo weight
            float score = dot / (fmaxf(sqrtf(ss), 1e-12f) * 128.f);
            out_w[n] = 0.5f * (score + 1.f) * sweights[n] * pw;
        }
    }
}

extern "C" void kernel_launch(void* const* d_in, const int* in_sizes, int n_in,
                              void* d_out, int out_size) {
    const float* coords  = (const float*)d_in[0];  // [16][2][4096]
    const float* weights = (const float*)d_in[1];  // [16][1][4096]
    const float* desc    = (const float*)d_in[2];  // [16][128][4096]
    float* out = (float*)d_out;                    // 65536 coords + 32768 weights

    size_t smem = (size_t)(CC * TN + CC * TM + TM * VS) * sizeof(float);
    cudaFuncSetAttribute(flash_kernel,
                         cudaFuncAttributeMaxDynamicSharedMemorySize, (int)smem);

    normalize_kernel<<<(16 * NN) / 256, 256>>>(desc);
    dim3 grid(NN / TN, PAIRS);
    flash_kernel<<<grid, NTHR, smem>>>(coords, weights, desc, out);
}

// round 6
// speedup vs baseline: 1.0679x; 1.0005x over previous
#include <cuda_runtime.h>
#include <math.h>

#define PAIRS 8
#define CC 128
#define NN 4096
#define TN 64
#define TM 64
#define VS 132   // V smem row stride: 128 desc + x + y + w + pad
#define NTHR 256

// Scratch for pre-normalized descriptors (x10 folded in so S = 100*cos)
__device__ float g_qn[PAIRS * CC * NN];
__device__ float g_kn[PAIRS * CC * NN];

__global__ void normalize_kernel(const float* __restrict__ desc) {
    int idx = blockIdx.x * blockDim.x + threadIdx.x;   // 0 .. 16*4096-1
    int b = idx >> 12;
    int n = idx & (NN - 1);
    const float* col = desc + (size_t)b * CC * NN + n;
    float ss = 0.f;
#pragma unroll 8
    for (int c = 0; c < CC; c++) { float v = col[(size_t)c * NN]; ss = fmaf(v, v, ss); }
    float inv = 10.f / fmaxf(sqrtf(ss), 1e-12f);
    float* dst = ((b & 1) ? g_kn : g_qn) + (size_t)(b >> 1) * CC * NN + n;
#pragma unroll 8
    for (int c = 0; c < CC; c++) dst[(size_t)c * NN] = col[(size_t)c * NN] * inv;
}

__global__ void __launch_bounds__(NTHR, 2)
flash_kernel(const float* __restrict__ coords,
             const float* __restrict__ weights,
             const float* __restrict__ desc,
             float* __restrict__ out)
{
    extern __shared__ float sm[];
    float* qs = sm;                    // [CC][TN]
    float* ks = qs + CC * TN;          // [CC][TM]
    float* vs = ks + CC * TM;          // [TM][VS]

    int p  = blockIdx.y;
    int n0 = blockIdx.x * TN;
    int tid = threadIdx.x;
    int tx = tid & 15;                 // 16 groups along m (GEMM1) / v-cols (GEMM2)
    int ty = tid >> 4;                 // 16 groups along n, 4 rows each

    const float* qsrc     = g_qn + (size_t)p * CC * NN;
    const float* ksrc     = g_kn + (size_t)p * CC * NN;
    const float* vdesc    = desc    + (size_t)(2 * p + 1) * CC * NN;
    const float* tcoords  = coords  + (size_t)(2 * p + 1) * 2 * NN;
    const float* tweights = weights + (size_t)(2 * p + 1) * NN;

    // Load Q tile (stays resident)
    for (int i = tid; i < CC * TN / 4; i += NTHR) {
        int c = i >> 4, nv = i & 15;
        *(float4*)(qs + c * TN + nv * 4) =
            *(const float4*)(qsrc + (size_t)c * NN + n0 + nv * 4);
    }

    float m_r[4], l_r[4], acc[4][8], acc_e[4];
#pragma unroll
    for (int r = 0; r < 4; r++) {
        m_r[r] = -1e30f; l_r[r] = 0.f; acc_e[r] = 0.f;
#pragma unroll
        for (int v = 0; v < 8; v++) acc[r][v] = 0.f;
    }

    for (int mt = 0; mt < NN / TM; ++mt) {
        int m0 = mt * TM;
        __syncthreads();   // previous iteration fully done with ks/vs

        // K tile
        for (int i = tid; i < CC * TM / 4; i += NTHR) {
            int c = i >> 4, mv = i & 15;
            *(float4*)(ks + c * TM + mv * 4) =
                *(const float4*)(ksrc + (size_t)c * NN + m0 + mv * 4);
        }
        // V tile: raw tgt_desc, transposed into [m][c]
        for (int i = tid; i < CC * TM / 4; i += NTHR) {
            int c = i >> 4, mv = i & 15;
            float4 g = *(const float4*)(vdesc + (size_t)c * NN + m0 + mv * 4);
            vs[(mv * 4 + 0) * VS + c] = g.x;
            vs[(mv * 4 + 1) * VS + c] = g.y;
            vs[(mv * 4 + 2) * VS + c] = g.z;
            vs[(mv * 4 + 3) * VS + c] = g.w;
        }
        if (tid < TM) {
            vs[tid * VS + 128] = tcoords[m0 + tid];
            vs[tid * VS + 129] = tcoords[NN + m0 + tid];
            vs[tid * VS + 130] = tweights[m0 + tid];
            vs[tid * VS + 131] = 0.f;
        }
        __syncthreads();

        // ---- GEMM1: S[4x4] = Q^T K over C=128 ----
        float s[4][4];
#pragma unroll
        for (int r = 0; r < 4; r++)
#pragma unroll
            for (int j = 0; j < 4; j++) s[r][j] = 0.f;

#pragma unroll 8
        for (int c = 0; c < CC; c++) {
            float4 qv = *(float4*)(qs + c * TN + ty * 4);
            float4 kv = *(float4*)(ks + c * TM + tx * 4);
            float qa[4] = {qv.x, qv.y, qv.z, qv.w};
            float ka[4] = {kv.x, kv.y, kv.z, kv.w};
#pragma unroll
            for (int r = 0; r < 4; r++)
#pragma unroll
                for (int j = 0; j < 4; j++)
                    s[r][j] = fmaf(qa[r], ka[j], s[r][j]);
        }

        // ---- online softmax (rows replicated across the 16 tx lanes) ----
#pragma unroll
        for (int r = 0; r < 4; r++) {
            float tmax = fmaxf(fmaxf(s[r][0], s[r][1]), fmaxf(s[r][2], s[r][3]));
#pragma unroll
            for (int off = 8; off; off >>= 1)
                tmax = fmaxf(tmax, __shfl_xor_sync(0xffffffffu, tmax, off, 16));
            float mn = fmaxf(m_r[r], tmax);
            float corr = __expf(m_r[r] - mn);
            m_r[r] = mn;
            float psum = 0.f;
#pragma unroll
            for (int j = 0; j < 4; j++) { s[r][j] = __expf(s[r][j] - mn); psum += s[r][j]; }
#pragma unroll
            for (int off = 8; off; off >>= 1)
                psum += __shfl_xor_sync(0xffffffffu, psum, off, 16);
            l_r[r] = l_r[r] * corr + psum;
#pragma unroll
            for (int v = 0; v < 8; v++) acc[r][v] *= corr;
            acc_e[r] *= corr;
        }

        // ---- GEMM2: acc += P * V, P distributed via shuffles ----
        // Lane u of each 16-lane tx group owns P columns m = u*4 .. u*4+3.
#pragma unroll 2
        for (int u = 0; u < 16; u++) {
#pragma unroll
            for (int jj = 0; jj < 4; jj++) {
                int m = u * 4 + jj;
                float4 va = *(float4*)(vs + m * VS + tx * 8);
                float4 vb = *(float4*)(vs + m * VS + tx * 8 + 4);
                float ve = (tx < 3) ? vs[m * VS + 128 + tx] : 0.f;
                float vv[8] = {va.x, va.y, va.z, va.w, vb.x, vb.y, vb.z, vb.w};
                float pr[4];
                pr[0] = __shfl_sync(0xffffffffu, s[0][jj], u, 16);
                pr[1] = __shfl_sync(0xffffffffu, s[1][jj], u, 16);
                pr[2] = __shfl_sync(0xffffffffu, s[2][jj], u, 16);
                pr[3] = __shfl_sync(0xffffffffu, s[3][jj], u, 16);
#pragma unroll
                for (int r = 0; r < 4; r++) {
#pragma unroll
                    for (int v = 0; v < 8; v++)
                        acc[r][v] = fmaf(pr[r], vv[v], acc[r][v]);
                    acc_e[r] = fmaf(pr[r], ve, acc_e[r]);
                }
            }
        }
    }

    // ---- epilogue ----
    // pseudo_desc normalization: acc/l normalized over c == acc normalized over c
    const float* sdesc    = desc    + (size_t)(2 * p) * CC * NN;   // raw src desc
    const float* sweights = weights + (size_t)(2 * p) * NN;
    float* out_c = out + (size_t)p * 2 * NN;
    float* out_w = out + (size_t)PAIRS * 2 * NN + (size_t)p * NN;

#pragma unroll
    for (int r = 0; r < 4; r++) {
        int n = n0 + ty * 4 + r;
        float ss = 0.f, dot = 0.f;
#pragma unroll
        for (int v = 0; v < 8; v++) {
            int c = tx * 8 + v;
            float a = acc[r][v];
            ss  = fmaf(a, a, ss);
            dot = fmaf(a, sdesc[(size_t)c * NN + n], dot);
        }
#pragma unroll
        for (int off = 8; off; off >>= 1) {
            ss  += __shfl_xor_sync(0xffffffffu, ss, off, 16);
            dot += __shfl_xor_sync(0xffffffffu, dot, off, 16);
        }
        float linv = 1.f / l_r[r];
        if (tx == 0) {
            out_c[n] = acc_e[r] * linv;                        // pseudo x
        } else if (tx == 1) {
            out_c[NN + n] = acc_e[r] * linv;                   // pseudo y
        } else if (tx == 2) {
            float pw = acc_e[r] * linv;                        // pseudo weight
            float score = dot / (fmaxf(sqrtf(ss), 1e-12f) * 128.f);
            out_w[n] = 0.5f * (score + 1.f) * sweights[n] * pw;
        }
    }
}

extern "C" void kernel_launch(void* const* d_in, const int* in_sizes, int n_in,
                              void* d_out, int out_size) {
    const float* coords  = (const float*)d_in[0];  // [16][2][4096]
    const float* weights = (const float*)d_in[1];  // [16][1][4096]
    const float* desc    = (const float*)d_in[2];  // [16][128][4096]
    float* out = (float*)d_out;                    // 65536 coords + 32768 weights

    size_t smem = (size_t)(CC * TN + CC * TM + TM * VS) * sizeof(float);
    cudaFuncSetAttribute(flash_kernel,
                         cudaFuncAttributeMaxDynamicSharedMemorySize, (int)smem);

    normalize_kernel<<<(16 * NN) / 256, 256>>>(desc);
    dim3 grid(NN / TN, PAIRS);
    flash_kernel<<<grid, NTHR, smem>>>(coords, weights, desc, out);
}

// round 8
// speedup vs baseline: 1.5144x; 1.4181x over previous
#include <cuda_runtime.h>
#include <math.h>
#include <stdint.h>

#define PAIRS 8
#define CC 128
#define NN 4096
#define TM 64          // keys per main-loop tile
#define TQ 128         // queries per CTA
#define NTHR 256

// ---------------- gmem scratch (packed mma fragments) ----------------
// Qp*: [p][g16=256][ks=16][lane=32] float4 (a0,a1,a2,a3)
// Kp*: [p][g8=512][kp=8][lane=32] float4 (b0_e,b1_e,b0_o,b1_o)
// Vp : [p][mt=64][cg=16][kp2=4][lane=32] float4 (b0_e,b1_e,b0_o,b1_o)
// g_st: [p][n][c] raw src desc (transposed), for epilogue dot
__device__ float4 g_qh[PAIRS*131072];
__device__ float4 g_ql[PAIRS*131072];
__device__ float4 g_kh[PAIRS*131072];
__device__ float4 g_kl[PAIRS*131072];
__device__ float4 g_vp[PAIRS*131072];
__device__ float  g_st[PAIRS*NN*CC];
__device__ float  g_inv[16*NN];

__device__ __forceinline__ float tf32r(float x) {
    float r; asm("cvt.rna.tf32.f32 %0, %1;" : "=f"(r) : "f"(x)); return r;
}

__device__ __forceinline__ void mma8(float* d, uint32_t a0, uint32_t a1,
                                     uint32_t a2, uint32_t a3,
                                     uint32_t b0, uint32_t b1) {
    asm volatile(
        "mma.sync.aligned.m16n8k8.row.col.f32.tf32.tf32.f32 "
        "{%0,%1,%2,%3},{%4,%5,%6,%7},{%8,%9},{%0,%1,%2,%3};"
        : "+f"(d[0]), "+f"(d[1]), "+f"(d[2]), "+f"(d[3])
        : "r"(a0), "r"(a1), "r"(a2), "r"(a3), "r"(b0), "r"(b1));
}

// ---------------- prep: norms ----------------
__global__ void norm_kernel(const float* __restrict__ desc) {
    int idx = blockIdx.x * blockDim.x + threadIdx.x;   // 16*4096
    int b = idx >> 12, n = idx & (NN - 1);
    const float* col = desc + (size_t)b * CC * NN + n;
    float ss = 0.f;
#pragma unroll 8
    for (int c = 0; c < CC; c++) { float v = col[(size_t)c * NN]; ss = fmaf(v, v, ss); }
    g_inv[idx] = 10.f / fmaxf(sqrtf(ss), 1e-12f);
}

// ---------------- prep: pack Q fragments (+ raw src transpose) ----------------
__global__ void packQ(const float* __restrict__ desc) {
    int gid = blockIdx.x * 256 + threadIdx.x;          // 1,048,576
    int lane = gid & 31, ks = (gid >> 5) & 15, g16 = (gid >> 9) & 255, p = gid >> 17;
    int r = lane >> 2, t = lane & 3;
    int n = g16 * 16 + r, c = ks * 8 + t;
    const float* src = desc + (size_t)(2 * p) * CC * NN;
    float i0 = g_inv[(2 * p) * NN + n], i1 = g_inv[(2 * p) * NN + n + 8];
    float v00 = src[(size_t)c * NN + n];
    float v10 = src[(size_t)c * NN + n + 8];
    float v01 = src[(size_t)(c + 4) * NN + n];
    float v11 = src[(size_t)(c + 4) * NN + n + 8];
    float* st = g_st + ((size_t)p * NN) * CC;
    st[(size_t)n * CC + c]           = v00;
    st[(size_t)(n + 8) * CC + c]     = v10;
    st[(size_t)n * CC + c + 4]       = v01;
    st[(size_t)(n + 8) * CC + c + 4] = v11;
    float q00 = v00 * i0, q10 = v10 * i1, q01 = v01 * i0, q11 = v11 * i1;
    float h00 = tf32r(q00), h10 = tf32r(q10), h01 = tf32r(q01), h11 = tf32r(q11);
    g_qh[gid] = make_float4(h00, h10, h01, h11);
    g_ql[gid] = make_float4(tf32r(q00 - h00), tf32r(q10 - h10),
                            tf32r(q01 - h01), tf32r(q11 - h11));
}

// ---------------- prep: pack K fragments ----------------
__global__ void packK(const float* __restrict__ desc) {
    int gid = blockIdx.x * 256 + threadIdx.x;          // 1,048,576
    int lane = gid & 31, kp = (gid >> 5) & 7, g8 = (gid >> 8) & 511, p = gid >> 17;
    int r = lane >> 2, t = lane & 3;
    int m = g8 * 8 + r, cb = kp * 16;
    const float* src = desc + (size_t)(2 * p + 1) * CC * NN;
    float inv = g_inv[(2 * p + 1) * NN + m];
    float v0 = src[(size_t)(cb + t) * NN + m] * inv;
    float v1 = src[(size_t)(cb + t + 4) * NN + m] * inv;
    float v2 = src[(size_t)(cb + 8 + t) * NN + m] * inv;
    float v3 = src[(size_t)(cb + 12 + t) * NN + m] * inv;
    float h0 = tf32r(v0), h1 = tf32r(v1), h2 = tf32r(v2), h3 = tf32r(v3);
    g_kh[gid] = make_float4(h0, h1, h2, h3);
    g_kl[gid] = make_float4(tf32r(v0 - h0), tf32r(v1 - h1),
                            tf32r(v2 - h2), tf32r(v3 - h3));
}

// ---------------- prep: pack V fragments (raw) ----------------
__global__ void packV(const float* __restrict__ desc) {
    int gid = blockIdx.x * 256 + threadIdx.x;          // 1,048,576
    int lane = gid & 31, kp2 = (gid >> 5) & 3, cg = (gid >> 7) & 15;
    int mt = (gid >> 11) & 63, p = gid >> 17;
    int r = lane >> 2, t = lane & 3;
    int c = cg * 8 + r, kb = mt * 64 + kp2 * 16;
    const float* src = desc + (size_t)(2 * p + 1) * CC * NN + (size_t)c * NN;
    g_vp[gid] = make_float4(src[kb + t], src[kb + t + 4],
                            src[kb + 8 + t], src[kb + 12 + t]);
}

// ---------------- main flash kernel (tf32 mma.sync) ----------------
// smem: Qh[8][16][32]f4 (64KB) | Ql (64KB) | P[8][16][68]f (34816B) | xs/ys/ws[2][64]
#define SMO_QL 65536
#define SMO_P  131072
#define SMO_XS 165888
#define SMO_YS 166400
#define SMO_WS 166912
#define SM_TOT 167424

__global__ void __launch_bounds__(NTHR, 1)
flash_mma(const float* __restrict__ coords,
          const float* __restrict__ weights,
          float* __restrict__ out)
{
    extern __shared__ char smraw[];
    float4* Qh_s = (float4*)smraw;
    float4* Ql_s = (float4*)(smraw + SMO_QL);
    float*  Pb   = (float*)(smraw + SMO_P);
    float*  xs   = (float*)(smraw + SMO_XS);
    float*  ys   = (float*)(smraw + SMO_YS);
    float*  ws   = (float*)(smraw + SMO_WS);

    int p  = blockIdx.y;
    int n0 = blockIdx.x * TQ;
    int tid = threadIdx.x;
    int w = tid >> 5, lane = tid & 31;
    int r = lane >> 2, t = lane & 3;
    float* Pw = Pb + w * (16 * 68);

    const float* tcoords  = coords  + (size_t)(2 * p + 1) * 2 * NN;
    const float* tweights = weights + (size_t)(2 * p + 1) * NN;

    // load this warp's Q fragments to smem (reused across all 64 tiles)
    {
        int g16w = blockIdx.x * 8 + w;
        size_t base = ((size_t)p * 256 + g16w) * 16;
#pragma unroll
        for (int ks = 0; ks < 16; ks++) {
            Qh_s[(w * 16 + ks) * 32 + lane] = g_qh[(base + ks) * 32 + lane];
            Ql_s[(w * 16 + ks) * 32 + lane] = g_ql[(base + ks) * 32 + lane];
        }
        __syncwarp();
    }

    float OUT[16][4];
#pragma unroll
    for (int cg = 0; cg < 16; cg++)
#pragma unroll
        for (int k = 0; k < 4; k++) OUT[cg][k] = 0.f;

    float mx0 = -1e30f, mx1 = -1e30f;
    float l0 = 0.f, l1 = 0.f;
    float ex0 = 0.f, ex1 = 0.f, ey0 = 0.f, ey1 = 0.f, ew0 = 0.f, ew1 = 0.f;

    for (int mt = 0; mt < 64; mt++) {
        int m0 = mt * TM;
        int buf = (mt & 1) * 64;
        if (tid < 64)       xs[buf + tid]        = tcoords[m0 + tid];
        else if (tid < 128) ys[buf + tid - 64]   = tcoords[NN + m0 + tid - 64];
        else if (tid < 192) ws[buf + tid - 128]  = tweights[m0 + tid - 128];
        __syncthreads();

        // ---- GEMM1: S[16q x 64k] = Qh*Kh + Ql*Kh + Qh*Kl ----
        float S[8][4];
#pragma unroll
        for (int nt = 0; nt < 8; nt++)
#pragma unroll
            for (int k = 0; k < 4; k++) S[nt][k] = 0.f;

        size_t kbase = (((size_t)p * 512 + mt * 8) * 8) * 32;
#pragma unroll
        for (int kp = 0; kp < 8; kp++) {
            float4 ahe = Qh_s[(w * 16 + 2 * kp) * 32 + lane];
            float4 aho = Qh_s[(w * 16 + 2 * kp + 1) * 32 + lane];
            float4 ale = Ql_s[(w * 16 + 2 * kp) * 32 + lane];
            float4 alo = Ql_s[(w * 16 + 2 * kp + 1) * 32 + lane];
            uint32_t AHE[4] = {__float_as_uint(ahe.x), __float_as_uint(ahe.y),
                               __float_as_uint(ahe.z), __float_as_uint(ahe.w)};
            uint32_t AHO[4] = {__float_as_uint(aho.x), __float_as_uint(aho.y),
                               __float_as_uint(aho.z), __float_as_uint(aho.w)};
            uint32_t ALE[4] = {__float_as_uint(ale.x), __float_as_uint(ale.y),
                               __float_as_uint(ale.z), __float_as_uint(ale.w)};
            uint32_t ALO[4] = {__float_as_uint(alo.x), __float_as_uint(alo.y),
                               __float_as_uint(alo.z), __float_as_uint(alo.w)};
#pragma unroll
            for (int nt = 0; nt < 8; nt++) {
                float4 kh = g_kh[kbase + ((size_t)nt * 8 + kp) * 32 + lane];
                float4 kl = g_kl[kbase + ((size_t)nt * 8 + kp) * 32 + lane];
                uint32_t khx = __float_as_uint(kh.x), khy = __float_as_uint(kh.y);
                uint32_t khz = __float_as_uint(kh.z), khw = __float_as_uint(kh.w);
                mma8(S[nt], AHE[0], AHE[1], AHE[2], AHE[3], khx, khy);
                mma8(S[nt], ALE[0], ALE[1], ALE[2], ALE[3], khx, khy);
                mma8(S[nt], AHE[0], AHE[1], AHE[2], AHE[3],
                     __float_as_uint(kl.x), __float_as_uint(kl.y));
                mma8(S[nt], AHO[0], AHO[1], AHO[2], AHO[3], khz, khw);
                mma8(S[nt], ALO[0], ALO[1], ALO[2], ALO[3], khz, khw);
                mma8(S[nt], AHO[0], AHO[1], AHO[2], AHO[3],
                     __float_as_uint(kl.z), __float_as_uint(kl.w));
            }
        }

        // ---- online softmax (rows r and r+8; cols 8nt+2t, +1) ----
        float rm0 = -1e30f, rm1 = -1e30f;
#pragma unroll
        for (int nt = 0; nt < 8; nt++) {
            rm0 = fmaxf(rm0, fmaxf(S[nt][0], S[nt][1]));
            rm1 = fmaxf(rm1, fmaxf(S[nt][2], S[nt][3]));
        }
        rm0 = fmaxf(rm0, __shfl_xor_sync(0xffffffffu, rm0, 1, 4));
        rm0 = fmaxf(rm0, __shfl_xor_sync(0xffffffffu, rm0, 2, 4));
        rm1 = fmaxf(rm1, __shfl_xor_sync(0xffffffffu, rm1, 1, 4));
        rm1 = fmaxf(rm1, __shfl_xor_sync(0xffffffffu, rm1, 2, 4));
        float mn0 = fmaxf(mx0, rm0), mn1 = fmaxf(mx1, rm1);
        float c0 = __expf(mx0 - mn0), c1 = __expf(mx1 - mn1);
        mx0 = mn0; mx1 = mn1;
        l0 *= c0; l1 *= c1;
        ex0 *= c0; ey0 *= c0; ew0 *= c0;
        ex1 *= c1; ey1 *= c1; ew1 *= c1;
#pragma unroll
        for (int cg = 0; cg < 16; cg++) {
            OUT[cg][0] *= c0; OUT[cg][1] *= c0;
            OUT[cg][2] *= c1; OUT[cg][3] *= c1;
        }
#pragma unroll
        for (int nt = 0; nt < 8; nt++) {
            int col = 8 * nt + 2 * t;
            float pa = __expf(S[nt][0] - mn0);
            float pb = __expf(S[nt][1] - mn0);
            float pc = __expf(S[nt][2] - mn1);
            float pd = __expf(S[nt][3] - mn1);
            float xa = xs[buf + col], xb = xs[buf + col + 1];
            float ya = ys[buf + col], yb = ys[buf + col + 1];
            float wa = ws[buf + col], wb = ws[buf + col + 1];
            l0 += pa + pb;  l1 += pc + pd;
            ex0 = fmaf(pa, xa, ex0); ex0 = fmaf(pb, xb, ex0);
            ex1 = fmaf(pc, xa, ex1); ex1 = fmaf(pd, xb, ex1);
            ey0 = fmaf(pa, ya, ey0); ey0 = fmaf(pb, yb, ey0);
            ey1 = fmaf(pc, ya, ey1); ey1 = fmaf(pd, yb, ey1);
            ew0 = fmaf(pa, wa, ew0); ew0 = fmaf(pb, wb, ew0);
            ew1 = fmaf(pc, wa, ew1); ew1 = fmaf(pd, wb, ew1);
            *(float2*)(Pw + r * 68 + col)       = make_float2(pa, pb);
            *(float2*)(Pw + (r + 8) * 68 + col) = make_float2(pc, pd);
        }
        __syncwarp();

        // ---- GEMM2: OUT[16q x 128c] += P[16q x 64k] * V[64k x 128c] ----
        size_t vbase = (((size_t)p * 64 + mt) * 16) * 4 * 32;
#pragma unroll
        for (int kp2 = 0; kp2 < 4; kp2++) {
            int cb = 16 * kp2;
            uint32_t ae0 = __float_as_uint(Pw[r * 68 + cb + t]);
            uint32_t ae1 = __float_as_uint(Pw[(r + 8) * 68 + cb + t]);
            uint32_t ae2 = __float_as_uint(Pw[r * 68 + cb + t + 4]);
            uint32_t ae3 = __float_as_uint(Pw[(r + 8) * 68 + cb + t + 4]);
            uint32_t ao0 = __float_as_uint(Pw[r * 68 + cb + 8 + t]);
            uint32_t ao1 = __float_as_uint(Pw[(r + 8) * 68 + cb + 8 + t]);
            uint32_t ao2 = __float_as_uint(Pw[r * 68 + cb + 12 + t]);
            uint32_t ao3 = __float_as_uint(Pw[(r + 8) * 68 + cb + 12 + t]);
#pragma unroll 8
            for (int cg = 0; cg < 16; cg++) {
                float4 v = g_vp[vbase + ((size_t)cg * 4 + kp2) * 32 + lane];
                mma8(OUT[cg], ae0, ae1, ae2, ae3,
                     __float_as_uint(v.x), __float_as_uint(v.y));
                mma8(OUT[cg], ao0, ao1, ao2, ao3,
                     __float_as_uint(v.z), __float_as_uint(v.w));
            }
        }
        __syncwarp();
    }

    // ---- epilogue ----
    int nq0 = n0 + w * 16 + r;          // row of c0/c1
    int nq1 = nq0 + 8;                  // row of c2/c3
    const float* st0 = g_st + ((size_t)p * NN + nq0) * CC;
    const float* st1 = g_st + ((size_t)p * NN + nq1) * CC;
    float ssq0 = 0.f, ssq1 = 0.f, dot0 = 0.f, dot1 = 0.f;
#pragma unroll
    for (int cg = 0; cg < 16; cg++) {
        int c = 8 * cg + 2 * t;
        float2 s0 = *(const float2*)(st0 + c);
        float2 s1 = *(const float2*)(st1 + c);
        float a = OUT[cg][0], b = OUT[cg][1];
        float d = OUT[cg][2], e = OUT[cg][3];
        ssq0 = fmaf(a, a, ssq0); ssq0 = fmaf(b, b, ssq0);
        ssq1 = fmaf(d, d, ssq1); ssq1 = fmaf(e, e, ssq1);
        dot0 = fmaf(a, s0.x, dot0); dot0 = fmaf(b, s0.y, dot0);
        dot1 = fmaf(d, s1.x, dot1); dot1 = fmaf(e, s1.y, dot1);
    }
#pragma unroll
    for (int off = 1; off <= 2; off <<= 1) {
        l0   += __shfl_xor_sync(0xffffffffu, l0, off, 4);
        l1   += __shfl_xor_sync(0xffffffffu, l1, off, 4);
        ex0  += __shfl_xor_sync(0xffffffffu, ex0, off, 4);
        ex1  += __shfl_xor_sync(0xffffffffu, ex1, off, 4);
        ey0  += __shfl_xor_sync(0xffffffffu, ey0, off, 4);
        ey1  += __shfl_xor_sync(0xffffffffu, ey1, off, 4);
        ew0  += __shfl_xor_sync(0xffffffffu, ew0, off, 4);
        ew1  += __shfl_xor_sync(0xffffffffu, ew1, off, 4);
        ssq0 += __shfl_xor_sync(0xffffffffu, ssq0, off, 4);
        ssq1 += __shfl_xor_sync(0xffffffffu, ssq1, off, 4);
        dot0 += __shfl_xor_sync(0xffffffffu, dot0, off, 4);
        dot1 += __shfl_xor_sync(0xffffffffu, dot1, off, 4);
    }
    float* out_c = out + (size_t)p * 2 * NN;
    float* out_w = out + (size_t)PAIRS * 2 * NN + (size_t)p * NN;
    const float* sweights = weights + (size_t)(2 * p) * NN;
    if (t == 0) {
        float linv = 1.f / l0;
        out_c[nq0]      = ex0 * linv;
        out_c[NN + nq0] = ey0 * linv;
        float score = dot0 / (fmaxf(sqrtf(ssq0), 1e-12f) * 128.f);
        out_w[nq0] = 0.5f * (score + 1.f) * sweights[nq0] * (ew0 * linv);
    } else if (t == 1) {
        float linv = 1.f / l1;
        out_c[nq1]      = ex1 * linv;
        out_c[NN + nq1] = ey1 * linv;
        float score = dot1 / (fmaxf(sqrtf(ssq1), 1e-12f) * 128.f);
        out_w[nq1] = 0.5f * (score + 1.f) * sweights[nq1] * (ew1 * linv);
    }
}

extern "C" void kernel_launch(void* const* d_in, const int* in_sizes, int n_in,
                              void* d_out, int out_size) {
    const float* coords  = (const float*)d_in[0];  // [16][2][4096]
    const float* weights = (const float*)d_in[1];  // [16][1][4096]
    const float* desc    = (const float*)d_in[2];  // [16][128][4096]
    float* out = (float*)d_out;

    cudaFuncSetAttribute(flash_mma,
                         cudaFuncAttributeMaxDynamicSharedMemorySize, SM_TOT);

    norm_kernel<<<(16 * NN) / 256, 256>>>(desc);
    packQ<<<4096, 256>>>(desc);
    packK<<<4096, 256>>>(desc);
    packV<<<4096, 256>>>(desc);
    dim3 grid(NN / TQ, PAIRS);
    flash_mma<<<grid, NTHR, SM_TOT>>>(coords, weights, out);
}

// round 10
// speedup vs baseline: 1.5494x; 1.0231x over previous
#include <cuda_runtime.h>
#include <math.h>
#include <stdint.h>

#define PAIRS 8
#define CC 128
#define NN 4096
#define TM 64          // keys per main-loop tile
#define TQ 128         // queries per CTA
#define NTHR 256

// ---------------- gmem scratch (packed mma fragments) ----------------
// g_qp: [p][g16=256][ks=16][lane=32] float4 (q00,q10,q01,q11) fp32 (normalized*10)
// g_kh/g_kl: [p][g8=512][kp=8][lane=32] float4 tf32 hi/lo
// g_vp : [p][mt=64][cg=16][kp2=4][lane=32] float4 raw
// g_st: [p][n][c] raw src desc (transposed), for epilogue dot
__device__ float4 g_qp[PAIRS*131072];
__device__ float4 g_kh[PAIRS*131072];
__device__ float4 g_kl[PAIRS*131072];
__device__ float4 g_vp[PAIRS*131072];
__device__ float  g_st[PAIRS*NN*CC];
__device__ float  g_inv[16*NN];

__device__ __forceinline__ float tf32r(float x) {
    float r; asm("cvt.rna.tf32.f32 %0, %1;" : "=f"(r) : "f"(x)); return r;
}

__device__ __forceinline__ void mma8(float* d, uint32_t a0, uint32_t a1,
                                     uint32_t a2, uint32_t a3,
                                     uint32_t b0, uint32_t b1) {
    asm volatile(
        "mma.sync.aligned.m16n8k8.row.col.f32.tf32.tf32.f32 "
        "{%0,%1,%2,%3},{%4,%5,%6,%7},{%8,%9},{%0,%1,%2,%3};"
        : "+f"(d[0]), "+f"(d[1]), "+f"(d[2]), "+f"(d[3])
        : "r"(a0), "r"(a1), "r"(a2), "r"(a3), "r"(b0), "r"(b1));
}

// ---------------- prep: norms ----------------
__global__ void norm_kernel(const float* __restrict__ desc) {
    int idx = blockIdx.x * blockDim.x + threadIdx.x;   // 16*4096
    int b = idx >> 12, n = idx & (NN - 1);
    const float* col = desc + (size_t)b * CC * NN + n;
    float ss = 0.f;
#pragma unroll 8
    for (int c = 0; c < CC; c++) { float v = col[(size_t)c * NN]; ss = fmaf(v, v, ss); }
    g_inv[idx] = 10.f / fmaxf(sqrtf(ss), 1e-12f);
}

// ---------------- prep: pack Q fragments fp32 (+ raw src transpose) ----------------
__global__ void packQ(const float* __restrict__ desc) {
    int gid = blockIdx.x * 256 + threadIdx.x;          // 1,048,576
    int lane = gid & 31, ks = (gid >> 5) & 15, g16 = (gid >> 9) & 255, p = gid >> 17;
    int r = lane >> 2, t = lane & 3;
    int n = g16 * 16 + r, c = ks * 8 + t;
    const float* src = desc + (size_t)(2 * p) * CC * NN;
    float i0 = g_inv[(2 * p) * NN + n], i1 = g_inv[(2 * p) * NN + n + 8];
    float v00 = src[(size_t)c * NN + n];
    float v10 = src[(size_t)c * NN + n + 8];
    float v01 = src[(size_t)(c + 4) * NN + n];
    float v11 = src[(size_t)(c + 4) * NN + n + 8];
    float* st = g_st + ((size_t)p * NN) * CC;
    st[(size_t)n * CC + c]           = v00;
    st[(size_t)(n + 8) * CC + c]     = v10;
    st[(size_t)n * CC + c + 4]       = v01;
    st[(size_t)(n + 8) * CC + c + 4] = v11;
    g_qp[gid] = make_float4(v00 * i0, v10 * i1, v01 * i0, v11 * i1);
}

// ---------------- prep: pack K fragments (tf32 hi/lo) ----------------
__global__ void packK(const float* __restrict__ desc) {
    int gid = blockIdx.x * 256 + threadIdx.x;          // 1,048,576
    int lane = gid & 31, kp = (gid >> 5) & 7, g8 = (gid >> 8) & 511, p = gid >> 17;
    int r = lane >> 2, t = lane & 3;
    int m = g8 * 8 + r, cb = kp * 16;
    const float* src = desc + (size_t)(2 * p + 1) * CC * NN;
    float inv = g_inv[(2 * p + 1) * NN + m];
    float v0 = src[(size_t)(cb + t) * NN + m] * inv;
    float v1 = src[(size_t)(cb + t + 4) * NN + m] * inv;
    float v2 = src[(size_t)(cb + 8 + t) * NN + m] * inv;
    float v3 = src[(size_t)(cb + 12 + t) * NN + m] * inv;
    float h0 = tf32r(v0), h1 = tf32r(v1), h2 = tf32r(v2), h3 = tf32r(v3);
    g_kh[gid] = make_float4(h0, h1, h2, h3);
    g_kl[gid] = make_float4(tf32r(v0 - h0), tf32r(v1 - h1),
                            tf32r(v2 - h2), tf32r(v3 - h3));
}

// ---------------- prep: pack V fragments (raw) ----------------
__global__ void packV(const float* __restrict__ desc) {
    int gid = blockIdx.x * 256 + threadIdx.x;          // 1,048,576
    int lane = gid & 31, kp2 = (gid >> 5) & 3, cg = (gid >> 7) & 15;
    int mt = (gid >> 11) & 63, p = gid >> 17;
    int r = lane >> 2, t = lane & 3;
    int c = cg * 8 + r, kb = mt * 64 + kp2 * 16;
    const float* src = desc + (size_t)(2 * p + 1) * CC * NN + (size_t)c * NN;
    g_vp[gid] = make_float4(src[kb + t], src[kb + t + 4],
                            src[kb + 8 + t], src[kb + 12 + t]);
}

// ---------------- main flash kernel (tf32 mma.sync, smem-staged K/V) ----------------
// smem bytes: Qs 65536 | Kh 32768 | Kl 32768 | V 32768 | P 34816 | xs/ys/ws 768
#define SMO_KH 65536
#define SMO_KL 98304
#define SMO_V  131072
#define SMO_P  163840
#define SMO_XS 198656
#define SMO_YS 198912
#define SMO_WS 199168
#define SM_TOT 199424

__global__ void __launch_bounds__(NTHR, 1)
flash_mma(const float* __restrict__ coords,
          const float* __restrict__ weights,
          float* __restrict__ out)
{
    extern __shared__ char smraw[];
    float4* Qs  = (float4*)smraw;
    float4* KHs = (float4*)(smraw + SMO_KH);
    float4* KLs = (float4*)(smraw + SMO_KL);
    float4* Vs  = (float4*)(smraw + SMO_V);
    float*  Pb  = (float*)(smraw + SMO_P);
    float*  xs  = (float*)(smraw + SMO_XS);
    float*  ys  = (float*)(smraw + SMO_YS);
    float*  ws  = (float*)(smraw + SMO_WS);

    int p  = blockIdx.y;
    int n0 = blockIdx.x * TQ;
    int tid = threadIdx.x;
    int w = tid >> 5, lane = tid & 31;
    int r = lane >> 2, t = lane & 3;
    float* Pw = Pb + w * (16 * 68);

    const float* tcoords  = coords  + (size_t)(2 * p + 1) * 2 * NN;
    const float* tweights = weights + (size_t)(2 * p + 1) * NN;

    // load this warp's Q fp32 fragments to smem (reused across all 64 tiles)
    {
        int g16w = blockIdx.x * 8 + w;
        size_t base = ((size_t)p * 256 + g16w) * 16;
#pragma unroll
        for (int ks = 0; ks < 16; ks++)
            Qs[(w * 16 + ks) * 32 + lane] = g_qp[(base + ks) * 32 + lane];
        __syncwarp();
    }

    float OUT[16][4];
#pragma unroll
    for (int cg = 0; cg < 16; cg++)
#pragma unroll
        for (int k = 0; k < 4; k++) OUT[cg][k] = 0.f;

    float mx0 = -1e30f, mx1 = -1e30f;
    float l0 = 0.f, l1 = 0.f;
    float ex0 = 0.f, ex1 = 0.f, ey0 = 0.f, ey1 = 0.f, ew0 = 0.f, ew1 = 0.f;

    for (int mt = 0; mt < 64; mt++) {
        int m0 = mt * TM;
        __syncthreads();   // all warps done with Vs / coords of previous tile

        // ---- stage K(hi/lo) + V fragment tiles into smem ----
        {
            size_t kb = (((size_t)p * 512 + mt * 8) * 8) * 32;       // 2048 float4
            size_t vb = (((size_t)p * 64 + mt) * 16) * 4 * 32;       // 2048 float4
#pragma unroll
            for (int i = 0; i < 8; i++) {
                int idx = i * 256 + tid;
                KHs[idx] = g_kh[kb + idx];
                KLs[idx] = g_kl[kb + idx];
                Vs[idx]  = g_vp[vb + idx];
            }
        }
        if (tid < 64)       xs[tid]        = tcoords[m0 + tid];
        else if (tid < 128) ys[tid - 64]   = tcoords[NN + m0 + tid - 64];
        else if (tid < 192) ws[tid - 128]  = tweights[m0 + tid - 128];
        __syncthreads();

        // ---- GEMM1: S[16q x 64k] = Qh*Kh + Ql*Kh + Qh*Kl ----
        float S[8][4];
#pragma unroll
        for (int nt = 0; nt < 8; nt++)
#pragma unroll
            for (int k = 0; k < 4; k++) S[nt][k] = 0.f;

#pragma unroll
        for (int kp = 0; kp < 8; kp++) {
            float4 qe = Qs[(w * 16 + 2 * kp) * 32 + lane];
            float4 qo = Qs[(w * 16 + 2 * kp + 1) * 32 + lane];
            float he0 = tf32r(qe.x), he1 = tf32r(qe.y), he2 = tf32r(qe.z), he3 = tf32r(qe.w);
            float ho0 = tf32r(qo.x), ho1 = tf32r(qo.y), ho2 = tf32r(qo.z), ho3 = tf32r(qo.w);
            uint32_t AHE[4] = {__float_as_uint(he0), __float_as_uint(he1),
                               __float_as_uint(he2), __float_as_uint(he3)};
            uint32_t AHO[4] = {__float_as_uint(ho0), __float_as_uint(ho1),
                               __float_as_uint(ho2), __float_as_uint(ho3)};
            uint32_t ALE[4] = {__float_as_uint(qe.x - he0), __float_as_uint(qe.y - he1),
                               __float_as_uint(qe.z - he2), __float_as_uint(qe.w - he3)};
            uint32_t ALO[4] = {__float_as_uint(qo.x - ho0), __float_as_uint(qo.y - ho1),
                               __float_as_uint(qo.z - ho2), __float_as_uint(qo.w - ho3)};
#pragma unroll
            for (int nt = 0; nt < 8; nt++) {
                float4 kh = KHs[(nt * 8 + kp) * 32 + lane];
                float4 kl = KLs[(nt * 8 + kp) * 32 + lane];
                uint32_t khx = __float_as_uint(kh.x), khy = __float_as_uint(kh.y);
                uint32_t khz = __float_as_uint(kh.z), khw = __float_as_uint(kh.w);
                mma8(S[nt], AHE[0], AHE[1], AHE[2], AHE[3], khx, khy);
                mma8(S[nt], ALE[0], ALE[1], ALE[2], ALE[3], khx, khy);
                mma8(S[nt], AHE[0], AHE[1], AHE[2], AHE[3],
                     __float_as_uint(kl.x), __float_as_uint(kl.y));
                mma8(S[nt], AHO[0], AHO[1], AHO[2], AHO[3], khz, khw);
                mma8(S[nt], ALO[0], ALO[1], ALO[2], ALO[3], khz, khw);
                mma8(S[nt], AHO[0], AHO[1], AHO[2], AHO[3],
                     __float_as_uint(kl.z), __float_as_uint(kl.w));
            }
        }

        // ---- online softmax (rows r and r+8; cols 8nt+2t, +1) ----
        float rm0 = -1e30f, rm1 = -1e30f;
#pragma unroll
        for (int nt = 0; nt < 8; nt++) {
            rm0 = fmaxf(rm0, fmaxf(S[nt][0], S[nt][1]));
            rm1 = fmaxf(rm1, fmaxf(S[nt][2], S[nt][3]));
        }
        rm0 = fmaxf(rm0, __shfl_xor_sync(0xffffffffu, rm0, 1, 4));
        rm0 = fmaxf(rm0, __shfl_xor_sync(0xffffffffu, rm0, 2, 4));
        rm1 = fmaxf(rm1, __shfl_xor_sync(0xffffffffu, rm1, 1, 4));
        rm1 = fmaxf(rm1, __shfl_xor_sync(0xffffffffu, rm1, 2, 4));
        float mn0 = fmaxf(mx0, rm0), mn1 = fmaxf(mx1, rm1);
        float c0 = __expf(mx0 - mn0), c1 = __expf(mx1 - mn1);
        mx0 = mn0; mx1 = mn1;
        l0 *= c0; l1 *= c1;
        ex0 *= c0; ey0 *= c0; ew0 *= c0;
        ex1 *= c1; ey1 *= c1; ew1 *= c1;
#pragma unroll
        for (int cg = 0; cg < 16; cg++) {
            OUT[cg][0] *= c0; OUT[cg][1] *= c0;
            OUT[cg][2] *= c1; OUT[cg][3] *= c1;
        }
#pragma unroll
        for (int nt = 0; nt < 8; nt++) {
            int col = 8 * nt + 2 * t;
            float pa = __expf(S[nt][0] - mn0);
            float pb = __expf(S[nt][1] - mn0);
            float pc = __expf(S[nt][2] - mn1);
            float pd = __expf(S[nt][3] - mn1);
            float xa = xs[col], xb = xs[col + 1];
            float ya = ys[col], yb = ys[col + 1];
            float wa = ws[col], wb = ws[col + 1];
            l0 += pa + pb;  l1 += pc + pd;
            ex0 = fmaf(pa, xa, ex0); ex0 = fmaf(pb, xb, ex0);
            ex1 = fmaf(pc, xa, ex1); ex1 = fmaf(pd, xb, ex1);
            ey0 = fmaf(pa, ya, ey0); ey0 = fmaf(pb, yb, ey0);
            ey1 = fmaf(pc, ya, ey1); ey1 = fmaf(pd, yb, ey1);
            ew0 = fmaf(pa, wa, ew0); ew0 = fmaf(pb, wb, ew0);
            ew1 = fmaf(pc, wa, ew1); ew1 = fmaf(pd, wb, ew1);
            *(float2*)(Pw + r * 68 + col)       = make_float2(pa, pb);
            *(float2*)(Pw + (r + 8) * 68 + col) = make_float2(pc, pd);
        }
        __syncwarp();

        // ---- GEMM2: OUT[16q x 128c] += P[16q x 64k] * V[64k x 128c] ----
#pragma unroll
        for (int kp2 = 0; kp2 < 4; kp2++) {
            int cb = 16 * kp2;
            uint32_t ae0 = __float_as_uint(Pw[r * 68 + cb + t]);
            uint32_t ae1 = __float_as_uint(Pw[(r + 8) * 68 + cb + t]);
            uint32_t ae2 = __float_as_uint(Pw[r * 68 + cb + t + 4]);
            uint32_t ae3 = __float_as_uint(Pw[(r + 8) * 68 + cb + t + 4]);
            uint32_t ao0 = __float_as_uint(Pw[r * 68 + cb + 8 + t]);
            uint32_t ao1 = __float_as_uint(Pw[(r + 8) * 68 + cb + 8 + t]);
            uint32_t ao2 = __float_as_uint(Pw[r * 68 + cb + 12 + t]);
            uint32_t ao3 = __float_as_uint(Pw[(r + 8) * 68 + cb + 12 + t]);
#pragma unroll 8
            for (int cg = 0; cg < 16; cg++) {
                float4 v = Vs[(cg * 4 + kp2) * 32 + lane];
                mma8(OUT[cg], ae0, ae1, ae2, ae3,
                     __float_as_uint(v.x), __float_as_uint(v.y));
                mma8(OUT[cg], ao0, ao1, ao2, ao3,
                     __float_as_uint(v.z), __float_as_uint(v.w));
            }
        }
        __syncwarp();
    }

    // ---- epilogue ----
    int nq0 = n0 + w * 16 + r;          // row of c0/c1
    int nq1 = nq0 + 8;                  // row of c2/c3
    const float* st0 = g_st + ((size_t)p * NN + nq0) * CC;
    const float* st1 = g_st + ((size_t)p * NN + nq1) * CC;
    float ssq0 = 0.f, ssq1 = 0.f, dot0 = 0.f, dot1 = 0.f;
#pragma unroll
    for (int cg = 0; cg < 16; cg++) {
        int c = 8 * cg + 2 * t;
        float2 s0 = *(const float2*)(st0 + c);
        float2 s1 = *(const float2*)(st1 + c);
        float a = OUT[cg][0], b = OUT[cg][1];
        float d = OUT[cg][2], e = OUT[cg][3];
        ssq0 = fmaf(a, a, ssq0); ssq0 = fmaf(b, b, ssq0);
        ssq1 = fmaf(d, d, ssq1); ssq1 = fmaf(e, e, ssq1);
        dot0 = fmaf(a, s0.x, dot0); dot0 = fmaf(b, s0.y, dot0);
        dot1 = fmaf(d, s1.x, dot1); dot1 = fmaf(e, s1.y, dot1);
    }
#pragma unroll
    for (int off = 1; off <= 2; off <<= 1) {
        l0   += __shfl_xor_sync(0xffffffffu, l0, off, 4);
        l1   += __shfl_xor_sync(0xffffffffu, l1, off, 4);
        ex0  += __shfl_xor_sync(0xffffffffu, ex0, off, 4);
        ex1  += __shfl_xor_sync(0xffffffffu, ex1, off, 4);
        ey0  += __shfl_xor_sync(0xffffffffu, ey0, off, 4);
        ey1  += __shfl_xor_sync(0xffffffffu, ey1, off, 4);
        ew0  += __shfl_xor_sync(0xffffffffu, ew0, off, 4);
        ew1  += __shfl_xor_sync(0xffffffffu, ew1, off, 4);
        ssq0 += __shfl_xor_sync(0xffffffffu, ssq0, off, 4);
        ssq1 += __shfl_xor_sync(0xffffffffu, ssq1, off, 4);
        dot0 += __shfl_xor_sync(0xffffffffu, dot0, off, 4);
        dot1 += __shfl_xor_sync(0xffffffffu, dot1, off, 4);
    }
    float* out_c = out + (size_t)p * 2 * NN;
    float* out_w = out + (size_t)PAIRS * 2 * NN + (size_t)p * NN;
    const float* sweights = weights + (size_t)(2 * p) * NN;
    if (t == 0) {
        float linv = 1.f / l0;
        out_c[nq0]      = ex0 * linv;
        out_c[NN + nq0] = ey0 * linv;
        float score = dot0 / (fmaxf(sqrtf(ssq0), 1e-12f) * 128.f);
        out_w[nq0] = 0.5f * (score + 1.f) * sweights[nq0] * (ew0 * linv);
    } else if (t == 1) {
        float linv = 1.f / l1;
        out_c[nq1]      = ex1 * linv;
        out_c[NN + nq1] = ey1 * linv;
        float score = dot1 / (fmaxf(sqrtf(ssq1), 1e-12f) * 128.f);
        out_w[nq1] = 0.5f * (score + 1.f) * sweights[nq1] * (ew1 * linv);
    }
}

extern "C" void kernel_launch(void* const* d_in, const int* in_sizes, int n_in,
                              void* d_out, int out_size) {
    const float* coords  = (const float*)d_in[0];  // [16][2][4096]
    const float* weights = (const float*)d_in[1];  // [16][1][4096]
    const float* desc    = (const float*)d_in[2];  // [16][128][4096]
    float* out = (float*)d_out;

    cudaFuncSetAttribute(flash_mma,
                         cudaFuncAttributeMaxDynamicSharedMemorySize, SM_TOT);

    norm_kernel<<<(16 * NN) / 256, 256>>>(desc);
    packQ<<<4096, 256>>>(desc);
    packK<<<4096, 256>>>(desc);
    packV<<<4096, 256>>>(desc);
    dim3 grid(NN / TQ, PAIRS);
    flash_mma<<<grid, NTHR, SM_TOT>>>(coords, weights, out);
}

// round 13
// speedup vs baseline: 3.6570x; 2.3603x over previous
#include <cuda_runtime.h>
#include <cuda_fp16.h>
#include <math.h>
#include <stdint.h>

#define PAIRS 8
#define CC 128
#define NN 4096
#define TM 64
#define TQ 128
#define NTHR 256
// fold 100x temp and log2(e) into the normalization: each side x 10*sqrt(log2 e)
#define SCALEF 12.0112238f

// ---------------- gmem scratch (packed fp16 mma fragments) ----------------
// g_qh/g_ql: [p][g16=256][ks=8][lane=32] uint4 = (a0,a1,a2,a3) half2-pairs
// g_kh/g_kl: [p][g8=512][ks=8][lane=32] uint2 = (b0,b1)
// g_vp:      [p][mt=64][cg=16][kp=4][lane=32] uint2 = (b0,b1)
// g_st: [p][n][c] raw src desc (transposed) for epilogue dot
__device__ uint4 g_qh[PAIRS*256*8*32];
__device__ uint4 g_ql[PAIRS*256*8*32];
__device__ uint2 g_kh[PAIRS*512*8*32];
__device__ uint2 g_kl[PAIRS*512*8*32];
__device__ uint2 g_vp[PAIRS*64*16*4*32];
__device__ float g_st[PAIRS*NN*CC];
__device__ float g_inv[16*NN];

__device__ __forceinline__ uint32_t packh2(float a, float b) {
    __half2 h = __floats2half2_rn(a, b);
    return *reinterpret_cast<uint32_t*>(&h);
}
__device__ __forceinline__ float hlo(float x) {   // x - fp16(x)
    return x - __half2float(__float2half_rn(x));
}
__device__ __forceinline__ float ex2f(float x) {
    float r; asm("ex2.approx.ftz.f32 %0, %1;" : "=f"(r) : "f"(x)); return r;
}
__device__ __forceinline__ void mma16(float* d, uint32_t a0, uint32_t a1,
                                      uint32_t a2, uint32_t a3,
                                      uint32_t b0, uint32_t b1) {
    asm volatile(
        "mma.sync.aligned.m16n8k16.row.col.f32.f16.f16.f32 "
        "{%0,%1,%2,%3},{%4,%5,%6,%7},{%8,%9},{%0,%1,%2,%3};"
        : "+f"(d[0]), "+f"(d[1]), "+f"(d[2]), "+f"(d[3])
        : "r"(a0), "r"(a1), "r"(a2), "r"(a3), "r"(b0), "r"(b1));
}

// ---------------- prep: norms ----------------
__global__ void norm_kernel(const float* __restrict__ desc) {
    int idx = blockIdx.x * blockDim.x + threadIdx.x;   // 16*4096
    int b = idx >> 12, n = idx & (NN - 1);
    const float* col = desc + (size_t)b * CC * NN + n;
    float ss = 0.f;
#pragma unroll 8
    for (int c = 0; c < CC; c++) { float v = col[(size_t)c * NN]; ss = fmaf(v, v, ss); }
    g_inv[idx] = SCALEF / fmaxf(sqrtf(ss), 1e-12f);
}

// ---------------- prep: Q fragments (fp16 hi/lo) + raw src transpose ----------------
__global__ void packQ(const float* __restrict__ desc) {
    int gid = blockIdx.x * 256 + threadIdx.x;          // 2^19
    int lane = gid & 31, ks = (gid >> 5) & 7, g16 = (gid >> 8) & 255, p = gid >> 16;
    int r = lane >> 2, t = lane & 3;
    int n = g16 * 16 + r, c = ks * 16 + 2 * t;
    const float* src = desc + (size_t)(2 * p) * CC * NN;
    float i0 = g_inv[(2 * p) * NN + n], i1 = g_inv[(2 * p) * NN + n + 8];
    float x00 = src[(size_t)c * NN + n],       x01 = src[(size_t)(c+1) * NN + n];
    float x10 = src[(size_t)c * NN + n + 8],   x11 = src[(size_t)(c+1) * NN + n + 8];
    float x20 = src[(size_t)(c+8) * NN + n],   x21 = src[(size_t)(c+9) * NN + n];
    float x30 = src[(size_t)(c+8) * NN + n+8], x31 = src[(size_t)(c+9) * NN + n+8];
    float* st = g_st + (size_t)p * NN * CC;
    st[(size_t)n * CC + c]           = x00;  st[(size_t)n * CC + c + 1]       = x01;
    st[(size_t)(n+8) * CC + c]       = x10;  st[(size_t)(n+8) * CC + c + 1]   = x11;
    st[(size_t)n * CC + c + 8]       = x20;  st[(size_t)n * CC + c + 9]       = x21;
    st[(size_t)(n+8) * CC + c + 8]   = x30;  st[(size_t)(n+8) * CC + c + 9]   = x31;
    float q00 = x00*i0, q01 = x01*i0, q10 = x10*i1, q11 = x11*i1;
    float q20 = x20*i0, q21 = x21*i0, q30 = x30*i1, q31 = x31*i1;
    g_qh[gid] = make_uint4(packh2(q00,q01), packh2(q10,q11),
                           packh2(q20,q21), packh2(q30,q31));
    g_ql[gid] = make_uint4(packh2(hlo(q00),hlo(q01)), packh2(hlo(q10),hlo(q11)),
                           packh2(hlo(q20),hlo(q21)), packh2(hlo(q30),hlo(q31)));
}

// ---------------- prep: K fragments (fp16 hi/lo) ----------------
__global__ void packK(const float* __restrict__ desc) {
    int gid = blockIdx.x * 256 + threadIdx.x;          // 2^20
    int lane = gid & 31, ks = (gid >> 5) & 7, g8 = (gid >> 8) & 511, p = gid >> 17;
    int r = lane >> 2, t = lane & 3;
    int m = g8 * 8 + r, c = ks * 16 + 2 * t;
    const float* src = desc + (size_t)(2 * p + 1) * CC * NN;
    float inv = g_inv[(2 * p + 1) * NN + m];
    float v0 = src[(size_t)c * NN + m] * inv;
    float v1 = src[(size_t)(c+1) * NN + m] * inv;
    float v2 = src[(size_t)(c+8) * NN + m] * inv;
    float v3 = src[(size_t)(c+9) * NN + m] * inv;
    g_kh[gid] = make_uint2(packh2(v0, v1), packh2(v2, v3));
    g_kl[gid] = make_uint2(packh2(hlo(v0), hlo(v1)), packh2(hlo(v2), hlo(v3)));
}

// ---------------- prep: V fragments (fp16 raw) ----------------
__global__ void packV(const float* __restrict__ desc) {
    int gid = blockIdx.x * 256 + threadIdx.x;          // 2^20
    int lane = gid & 31, kp = (gid >> 5) & 3, cg = (gid >> 7) & 15;
    int mt = (gid >> 11) & 63, p = gid >> 17;
    int r = lane >> 2, t = lane & 3;
    int ch = cg * 8 + r, key = mt * 64 + kp * 16 + 2 * t;
    const float* src = desc + (size_t)(2 * p + 1) * CC * NN + (size_t)ch * NN;
    g_vp[gid] = make_uint2(packh2(src[key], src[key + 1]),
                           packh2(src[key + 8], src[key + 9]));
}

// ---------------- main flash kernel (fp16 mma.sync, P in registers) ----------------
#define SMO_QL 32768
#define SMO_KH 65536
#define SMO_KL 81920
#define SMO_V  98304
#define SMO_XS 114688
#define SMO_YS 114944
#define SMO_WS 115200
#define SM_TOT 115456

__global__ void __launch_bounds__(NTHR, 1)
flash_mma(const float* __restrict__ coords,
          const float* __restrict__ weights,
          float* __restrict__ out)
{
    extern __shared__ char smraw[];
    uint4* QHs = (uint4*)smraw;
    uint4* QLs = (uint4*)(smraw + SMO_QL);
    uint2* KHs = (uint2*)(smraw + SMO_KH);
    uint2* KLs = (uint2*)(smraw + SMO_KL);
    uint2* Vs  = (uint2*)(smraw + SMO_V);
    float* xs  = (float*)(smraw + SMO_XS);
    float* ys  = (float*)(smraw + SMO_YS);
    float* ws  = (float*)(smraw + SMO_WS);

    int p  = blockIdx.y;
    int n0 = blockIdx.x * TQ;
    int tid = threadIdx.x;
    int w = tid >> 5, lane = tid & 31;
    int r = lane >> 2, t = lane & 3;

    const float* tcoords  = coords  + (size_t)(2 * p + 1) * 2 * NN;
    const float* tweights = weights + (size_t)(2 * p + 1) * NN;

    // this warp's Q fragments -> smem (reused over all 64 key tiles)
    {
        size_t base = ((size_t)(p * 256 + blockIdx.x * 8 + w)) * 8;
#pragma unroll
        for (int ks = 0; ks < 8; ks++) {
            QHs[(w * 8 + ks) * 32 + lane] = g_qh[(base + ks) * 32 + lane];
            QLs[(w * 8 + ks) * 32 + lane] = g_ql[(base + ks) * 32 + lane];
        }
        __syncwarp();
    }

    float OUT[16][4];
#pragma unroll
    for (int cg = 0; cg < 16; cg++)
#pragma unroll
        for (int k = 0; k < 4; k++) OUT[cg][k] = 0.f;

    float mx0 = -1e30f, mx1 = -1e30f;
    float l0 = 0.f, l1 = 0.f;
    float ex0 = 0.f, ex1 = 0.f, ey0 = 0.f, ey1 = 0.f, ew0 = 0.f, ew1 = 0.f;

    for (int mt = 0; mt < 64; mt++) {
        int m0 = mt * TM;
        __syncthreads();   // previous tile fully consumed

        // ---- stage K(hi/lo) + V (fp16 fragments) ----
        {
            const uint4* kh = (const uint4*)(g_kh + ((size_t)(p * 512 + mt * 8)) * 8 * 32);
            const uint4* kl = (const uint4*)(g_kl + ((size_t)(p * 512 + mt * 8)) * 8 * 32);
            const uint4* vv = (const uint4*)(g_vp + ((size_t)(p * 64 + mt)) * 16 * 4 * 32);
            uint4* KH4 = (uint4*)KHs; uint4* KL4 = (uint4*)KLs; uint4* V4 = (uint4*)Vs;
#pragma unroll
            for (int i = 0; i < 4; i++) {
                int idx = i * 256 + tid;
                KH4[idx] = kh[idx];
                KL4[idx] = kl[idx];
                V4[idx]  = vv[idx];
            }
        }
        if (tid < 64)       xs[tid]       = tcoords[m0 + tid];
        else if (tid < 128) ys[tid - 64]  = tcoords[NN + m0 + tid - 64];
        else if (tid < 192) ws[tid - 128] = tweights[m0 + tid - 128];
        __syncthreads();

        // ---- GEMM1: S = Qh*Kh + Ql*Kh + Qh*Kl (fp16, logits in log2 domain) ----
        float S[8][4];
#pragma unroll
        for (int nt = 0; nt < 8; nt++)
#pragma unroll
            for (int k = 0; k < 4; k++) S[nt][k] = 0.f;

#pragma unroll
        for (int ks = 0; ks < 8; ks++) {
            uint4 qh = QHs[(w * 8 + ks) * 32 + lane];
            uint4 ql = QLs[(w * 8 + ks) * 32 + lane];
#pragma unroll
            for (int nt = 0; nt < 8; nt++) {
                uint2 kh = KHs[(nt * 8 + ks) * 32 + lane];
                uint2 kl = KLs[(nt * 8 + ks) * 32 + lane];
                mma16(S[nt], qh.x, qh.y, qh.z, qh.w, kh.x, kh.y);
                mma16(S[nt], ql.x, ql.y, ql.z, ql.w, kh.x, kh.y);
                mma16(S[nt], qh.x, qh.y, qh.z, qh.w, kl.x, kl.y);
            }
        }

        // ---- online softmax (log2 domain; rows r, r+8; cols 8nt+2t,+1) ----
        float rm0 = -1e30f, rm1 = -1e30f;
#pragma unroll
        for (int nt = 0; nt < 8; nt++) {
            rm0 = fmaxf(rm0, fmaxf(S[nt][0], S[nt][1]));
            rm1 = fmaxf(rm1, fmaxf(S[nt][2], S[nt][3]));
        }
        rm0 = fmaxf(rm0, __shfl_xor_sync(0xffffffffu, rm0, 1, 4));
        rm0 = fmaxf(rm0, __shfl_xor_sync(0xffffffffu, rm0, 2, 4));
        rm1 = fmaxf(rm1, __shfl_xor_sync(0xffffffffu, rm1, 1, 4));
        rm1 = fmaxf(rm1, __shfl_xor_sync(0xffffffffu, rm1, 2, 4));
        float mn0 = fmaxf(mx0, rm0), mn1 = fmaxf(mx1, rm1);
        float c0 = ex2f(mx0 - mn0), c1 = ex2f(mx1 - mn1);
        mx0 = mn0; mx1 = mn1;
        l0 *= c0; l1 *= c1;
        ex0 *= c0; ey0 *= c0; ew0 *= c0;
        ex1 *= c1; ey1 *= c1; ew1 *= c1;
#pragma unroll
        for (int cg = 0; cg < 16; cg++) {
            OUT[cg][0] *= c0; OUT[cg][1] *= c0;
            OUT[cg][2] *= c1; OUT[cg][3] *= c1;
        }
#pragma unroll
        for (int nt = 0; nt < 8; nt++) {
            int col = 8 * nt + 2 * t;
            float pa = ex2f(S[nt][0] - mn0);
            float pb = ex2f(S[nt][1] - mn0);
            float pc = ex2f(S[nt][2] - mn1);
            float pd = ex2f(S[nt][3] - mn1);
            S[nt][0] = pa; S[nt][1] = pb; S[nt][2] = pc; S[nt][3] = pd;
            float xa = xs[col], xb = xs[col + 1];
            float ya = ys[col], yb = ys[col + 1];
            float wa = ws[col], wb = ws[col + 1];
            l0 += pa + pb;  l1 += pc + pd;
            ex0 = fmaf(pa, xa, ex0); ex0 = fmaf(pb, xb, ex0);
            ex1 = fmaf(pc, xa, ex1); ex1 = fmaf(pd, xb, ex1);
            ey0 = fmaf(pa, ya, ey0); ey0 = fmaf(pb, yb, ey0);
            ey1 = fmaf(pc, ya, ey1); ey1 = fmaf(pd, yb, ey1);
            ew0 = fmaf(pa, wa, ew0); ew0 = fmaf(pb, wb, ew0);
            ew1 = fmaf(pc, wa, ew1); ew1 = fmaf(pd, wb, ew1);
        }

        // ---- GEMM2: OUT += P * V  (P straight from D-fragments; no smem) ----
#pragma unroll
        for (int kp = 0; kp < 4; kp++) {
            uint32_t a0 = packh2(S[2*kp][0],   S[2*kp][1]);
            uint32_t a1 = packh2(S[2*kp][2],   S[2*kp][3]);
            uint32_t a2 = packh2(S[2*kp+1][0], S[2*kp+1][1]);
            uint32_t a3 = packh2(S[2*kp+1][2], S[2*kp+1][3]);
#pragma unroll
            for (int cg = 0; cg < 16; cg++) {
                uint2 v = Vs[(cg * 4 + kp) * 32 + lane];
                mma16(OUT[cg], a0, a1, a2, a3, v.x, v.y);
            }
        }
    }

    // ---- epilogue ----
    int nq0 = n0 + w * 16 + r;
    int nq1 = nq0 + 8;
    const float* st0 = g_st + ((size_t)p * NN + nq0) * CC;
    const float* st1 = g_st + ((size_t)p * NN + nq1) * CC;
    float ssq0 = 0.f, ssq1 = 0.f, dot0 = 0.f, dot1 = 0.f;
#pragma unroll
    for (int cg = 0; cg < 16; cg++) {
        int c = 8 * cg + 2 * t;
        float2 s0 = *(const float2*)(st0 + c);
        float2 s1 = *(const float2*)(st1 + c);
        float a = OUT[cg][0], b = OUT[cg][1];
        float d = OUT[cg][2], e = OUT[cg][3];
        ssq0 = fmaf(a, a, ssq0); ssq0 = fmaf(b, b, ssq0);
        ssq1 = fmaf(d, d, ssq1); ssq1 = fmaf(e, e, ssq1);
        dot0 = fmaf(a, s0.x, dot0); dot0 = fmaf(b, s0.y, dot0);
        dot1 = fmaf(d, s1.x, dot1); dot1 = fmaf(e, s1.y, dot1);
    }
#pragma unroll
    for (int off = 1; off <= 2; off <<= 1) {
        l0   += __shfl_xor_sync(0xffffffffu, l0, off, 4);
        l1   += __shfl_xor_sync(0xffffffffu, l1, off, 4);
        ex0  += __shfl_xor_sync(0xffffffffu, ex0, off, 4);
        ex1  += __shfl_xor_sync(0xffffffffu, ex1, off, 4);
        ey0  += __shfl_xor_sync(0xffffffffu, ey0, off, 4);
        ey1  += __shfl_xor_sync(0xffffffffu, ey1, off, 4);
        ew0  += __shfl_xor_sync(0xffffffffu, ew0, off, 4);
        ew1  += __shfl_xor_sync(0xffffffffu, ew1, off, 4);
        ssq0 += __shfl_xor_sync(0xffffffffu, ssq0, off, 4);
        ssq1 += __shfl_xor_sync(0xffffffffu, ssq1, off, 4);
        dot0 += __shfl_xor_sync(0xffffffffu, dot0, off, 4);
        dot1 += __shfl_xor_sync(0xffffffffu, dot1, off, 4);
    }
    float* out_c = out + (size_t)p * 2 * NN;
    float* out_w = out + (size_t)PAIRS * 2 * NN + (size_t)p * NN;
    const float* sweights = weights + (size_t)(2 * p) * NN;
    if (t == 0) {
        float linv = 1.f / l0;
        out_c[nq0]      = ex0 * linv;
        out_c[NN + nq0] = ey0 * linv;
        float score = dot0 / (fmaxf(sqrtf(ssq0), 1e-12f) * 128.f);
        out_w[nq0] = 0.5f * (score + 1.f) * sweights[nq0] * (ew0 * linv);
    } else if (t == 1) {
        float linv = 1.f / l1;
        out_c[nq1]      = ex1 * linv;
        out_c[NN + nq1] = ey1 * linv;
        float score = dot1 / (fmaxf(sqrtf(ssq1), 1e-12f) * 128.f);
        out_w[nq1] = 0.5f * (score + 1.f) * sweights[nq1] * (ew1 * linv);
    }
}

extern "C" void kernel_launch(void* const* d_in, const int* in_sizes, int n_in,
                              void* d_out, int out_size) {
    const float* coords  = (const float*)d_in[0];  // [16][2][4096]
    const float* weights = (const float*)d_in[1];  // [16][1][4096]
    const float* desc    = (const float*)d_in[2];  // [16][128][4096]
    float* out = (float*)d_out;

    cudaFuncSetAttribute(flash_mma,
                         cudaFuncAttributeMaxDynamicSharedMemorySize, SM_TOT);

    norm_kernel<<<(16 * NN) / 256, 256>>>(desc);
    packQ<<<2048, 256>>>(desc);
    packK<<<4096, 256>>>(desc);
    packV<<<4096, 256>>>(desc);
    dim3 grid(NN / TQ, PAIRS);
    flash_mma<<<grid, NTHR, SM_TOT>>>(coords, weights, out);
}

// round 16
// speedup vs baseline: 6.1901x; 1.6927x over previous
#include <cuda_runtime.h>
#include <cuda_fp16.h>
#include <math.h>
#include <stdint.h>

#define PAIRS 8
#define CC 128
#define NN 4096
#define TM 64
#define TQ 128
#define NTHR 256
// fold 100x temp and log2(e) into the normalization: each side x 10*sqrt(log2 e)
#define SCALEF 12.0112238f

// ---------------- gmem scratch (packed fp16 mma fragments) ----------------
// g_qh/g_ql: [p][g16=256][ks=8][lane=32] uint4 (a0..a3 half2)
// g_khl:     [p][g8=512][ks=8][lane=32] uint4 = (kh0,kh1,kl0,kl1)
// g_vp:      [p][mt=64][cg=16][j=2][lane=32] uint4 = (v(kp=2j).b0,b1, v(kp=2j+1).b0,b1)
// g_st: [p][n][c] raw src desc (transposed) for epilogue dot
__device__ uint4 g_qh[PAIRS*256*8*32];
__device__ uint4 g_ql[PAIRS*256*8*32];
__device__ uint4 g_khl[PAIRS*512*8*32];
__device__ uint4 g_vp[PAIRS*64*16*2*32];
__device__ float g_st[PAIRS*NN*CC];
__device__ float g_inv[16*NN];

__device__ __forceinline__ uint32_t packh2(float a, float b) {
    __half2 h = __floats2half2_rn(a, b);
    return *reinterpret_cast<uint32_t*>(&h);
}
__device__ __forceinline__ float hlo(float x) { return x - __half2float(__float2half_rn(x)); }
__device__ __forceinline__ float ex2f(float x) {
    float r; asm("ex2.approx.ftz.f32 %0, %1;" : "=f"(r) : "f"(x)); return r;
}
__device__ __forceinline__ void mma16(float* d, uint32_t a0, uint32_t a1,
                                      uint32_t a2, uint32_t a3,
                                      uint32_t b0, uint32_t b1) {
    asm volatile(
        "mma.sync.aligned.m16n8k16.row.col.f32.f16.f16.f32 "
        "{%0,%1,%2,%3},{%4,%5,%6,%7},{%8,%9},{%0,%1,%2,%3};"
        : "+f"(d[0]), "+f"(d[1]), "+f"(d[2]), "+f"(d[3])
        : "r"(a0), "r"(a1), "r"(a2), "r"(a3), "r"(b0), "r"(b1));
}
__device__ __forceinline__ uint32_t smem_u32(const void* p) {
    uint32_t a;
    asm("{ .reg .u64 t; cvta.to.shared.u64 t, %1; cvt.u32.u64 %0, t; }" : "=r"(a) : "l"(p));
    return a;
}
#define CP_ASYNC16(saddr, gptr) \
    asm volatile("cp.async.cg.shared.global [%0], [%1], 16;" :: "r"(saddr), "l"(gptr))
#define CP_COMMIT() asm volatile("cp.async.commit_group;" ::: "memory")
#define CP_WAIT0()  asm volatile("cp.async.wait_group 0;" ::: "memory")

// ---------------- prep: norms ----------------
__global__ void norm_kernel(const float* __restrict__ desc) {
    int idx = blockIdx.x * blockDim.x + threadIdx.x;   // 16*4096
    int b = idx >> 12, n = idx & (NN - 1);
    const float* col = desc + (size_t)b * CC * NN + n;
    float ss = 0.f;
#pragma unroll 8
    for (int c = 0; c < CC; c++) { float v = col[(size_t)c * NN]; ss = fmaf(v, v, ss); }
    g_inv[idx] = SCALEF / fmaxf(sqrtf(ss), 1e-12f);
}

// ---------------- prep: Q fragments (fp16 hi/lo) + raw src transpose ----------------
__global__ void packQ(const float* __restrict__ desc) {
    int gid = blockIdx.x * 256 + threadIdx.x;          // 2^19
    int lane = gid & 31, ks = (gid >> 5) & 7, g16 = (gid >> 8) & 255, p = gid >> 16;
    int r = lane >> 2, t = lane & 3;
    int n = g16 * 16 + r, c = ks * 16 + 2 * t;
    const float* src = desc + (size_t)(2 * p) * CC * NN;
    float i0 = g_inv[(2 * p) * NN + n], i1 = g_inv[(2 * p) * NN + n + 8];
    float x00 = src[(size_t)c * NN + n],       x01 = src[(size_t)(c+1) * NN + n];
    float x10 = src[(size_t)c * NN + n + 8],   x11 = src[(size_t)(c+1) * NN + n + 8];
    float x20 = src[(size_t)(c+8) * NN + n],   x21 = src[(size_t)(c+9) * NN + n];
    float x30 = src[(size_t)(c+8) * NN + n+8], x31 = src[(size_t)(c+9) * NN + n+8];
    float* st = g_st + (size_t)p * NN * CC;
    st[(size_t)n * CC + c]           = x00;  st[(size_t)n * CC + c + 1]       = x01;
    st[(size_t)(n+8) * CC + c]       = x10;  st[(size_t)(n+8) * CC + c + 1]   = x11;
    st[(size_t)n * CC + c + 8]       = x20;  st[(size_t)n * CC + c + 9]       = x21;
    st[(size_t)(n+8) * CC + c + 8]   = x30;  st[(size_t)(n+8) * CC + c + 9]   = x31;
    float q00 = x00*i0, q01 = x01*i0, q10 = x10*i1, q11 = x11*i1;
    float q20 = x20*i0, q21 = x21*i0, q30 = x30*i1, q31 = x31*i1;
    g_qh[gid] = make_uint4(packh2(q00,q01), packh2(q10,q11),
                           packh2(q20,q21), packh2(q30,q31));
    g_ql[gid] = make_uint4(packh2(hlo(q00),hlo(q01)), packh2(hlo(q10),hlo(q11)),
                           packh2(hlo(q20),hlo(q21)), packh2(hlo(q30),hlo(q31)));
}

// ---------------- prep: K fragments (fp16 hi+lo packed in one uint4) ----------------
__global__ void packK(const float* __restrict__ desc) {
    int gid = blockIdx.x * 256 + threadIdx.x;          // 2^20
    int lane = gid & 31, ks = (gid >> 5) & 7, g8 = (gid >> 8) & 511, p = gid >> 17;
    int r = lane >> 2, t = lane & 3;
    int m = g8 * 8 + r, c = ks * 16 + 2 * t;
    const float* src = desc + (size_t)(2 * p + 1) * CC * NN;
    float inv = g_inv[(2 * p + 1) * NN + m];
    float v0 = src[(size_t)c * NN + m] * inv;
    float v1 = src[(size_t)(c+1) * NN + m] * inv;
    float v2 = src[(size_t)(c+8) * NN + m] * inv;
    float v3 = src[(size_t)(c+9) * NN + m] * inv;
    g_khl[gid] = make_uint4(packh2(v0, v1), packh2(v2, v3),
                            packh2(hlo(v0), hlo(v1)), packh2(hlo(v2), hlo(v3)));
}

// ---------------- prep: V fragments (fp16, kp-pairs packed) ----------------
__global__ void packV(const float* __restrict__ desc) {
    int gid = blockIdx.x * 256 + threadIdx.x;          // 2^19
    int lane = gid & 31, j = (gid >> 5) & 1, cg = (gid >> 6) & 15;
    int mt = (gid >> 10) & 63, p = gid >> 16;
    int r = lane >> 2, t = lane & 3;
    int ch = cg * 8 + r;
    int key0 = mt * 64 + (2 * j) * 16 + 2 * t;
    int key1 = key0 + 16;
    const float* src = desc + (size_t)(2 * p + 1) * CC * NN + (size_t)ch * NN;
    g_vp[gid] = make_uint4(packh2(src[key0], src[key0 + 1]),
                           packh2(src[key0 + 8], src[key0 + 9]),
                           packh2(src[key1], src[key1 + 1]),
                           packh2(src[key1 + 8], src[key1 + 9]));
}

// ---------------- main flash kernel ----------------
#define SMO_QL  32768
#define SMO_KHL 65536
#define SMO_V   98304
#define SMO_XS  114688
#define SMO_YS  114944
#define SMO_WS  115200
#define SM_TOT  115456

__global__ void __launch_bounds__(NTHR, 2)
flash_mma(const float* __restrict__ coords,
          const float* __restrict__ weights,
          float* __restrict__ out)
{
    extern __shared__ char smraw[];
    uint4* QHs  = (uint4*)smraw;
    uint4* QLs  = (uint4*)(smraw + SMO_QL);
    uint4* KHLs = (uint4*)(smraw + SMO_KHL);
    uint4* Vs   = (uint4*)(smraw + SMO_V);
    float* xs   = (float*)(smraw + SMO_XS);
    float* ys   = (float*)(smraw + SMO_YS);
    float* ws   = (float*)(smraw + SMO_WS);
    uint32_t sb = smem_u32(smraw);

    int p  = blockIdx.y;
    int n0 = blockIdx.x * TQ;
    int tid = threadIdx.x;
    int w = tid >> 5, lane = tid & 31;
    int r = lane >> 2, t = lane & 3;

    const float* tcoords  = coords  + (size_t)(2 * p + 1) * 2 * NN;
    const float* tweights = weights + (size_t)(2 * p + 1) * NN;

    // this warp's Q fragments -> smem (reused over all 64 key tiles)
    {
        size_t base = ((size_t)(p * 256 + blockIdx.x * 8 + w)) * 8;
#pragma unroll
        for (int ks = 0; ks < 8; ks++) {
            QHs[(w * 8 + ks) * 32 + lane] = g_qh[(base + ks) * 32 + lane];
            QLs[(w * 8 + ks) * 32 + lane] = g_ql[(base + ks) * 32 + lane];
        }
        __syncwarp();
    }

    float OUT[16][4];
#pragma unroll
    for (int cg = 0; cg < 16; cg++)
#pragma unroll
        for (int k = 0; k < 4; k++) OUT[cg][k] = 0.f;

    float mx0 = -1e30f, mx1 = -1e30f;
    float l0 = 0.f, l1 = 0.f;
    float ex0 = 0.f, ex1 = 0.f, ey0 = 0.f, ey1 = 0.f, ew0 = 0.f, ew1 = 0.f;

    for (int mt = 0; mt < 64; mt++) {
        int m0 = mt * TM;
        __syncthreads();   // previous tile fully consumed

        // ---- stage K(hi|lo) + V via cp.async ----
        {
            const uint4* khg = g_khl + ((size_t)(p * 512 + mt * 8)) * 8 * 32;
            const uint4* vg  = g_vp  + ((size_t)(p * 64 + mt)) * 16 * 2 * 32;
#pragma unroll
            for (int i = 0; i < 8; i++) {
                int idx = i * 256 + tid;
                CP_ASYNC16(sb + SMO_KHL + idx * 16, khg + idx);
            }
#pragma unroll
            for (int i = 0; i < 4; i++) {
                int idx = i * 256 + tid;
                CP_ASYNC16(sb + SMO_V + idx * 16, vg + idx);
            }
            CP_COMMIT();
        }
        if (tid < 64)       xs[tid]       = tcoords[m0 + tid];
        else if (tid < 128) ys[tid - 64]  = tcoords[NN + m0 + tid - 64];
        else if (tid < 192) ws[tid - 128] = tweights[m0 + tid - 128];
        CP_WAIT0();
        __syncthreads();

        // ---- GEMM1: S = Qh*Kh + Ql*Kh + Qh*Kl (logits in log2 domain) ----
        float S[8][4];
#pragma unroll
        for (int nt = 0; nt < 8; nt++)
#pragma unroll
            for (int k = 0; k < 4; k++) S[nt][k] = 0.f;

#pragma unroll
        for (int ks = 0; ks < 8; ks++) {
            uint4 qh = QHs[(w * 8 + ks) * 32 + lane];
            uint4 ql = QLs[(w * 8 + ks) * 32 + lane];
#pragma unroll
            for (int nt = 0; nt < 8; nt++) {
                uint4 k4 = KHLs[(nt * 8 + ks) * 32 + lane];
                mma16(S[nt], qh.x, qh.y, qh.z, qh.w, k4.x, k4.y);
                mma16(S[nt], ql.x, ql.y, ql.z, ql.w, k4.x, k4.y);
                mma16(S[nt], qh.x, qh.y, qh.z, qh.w, k4.z, k4.w);
            }
        }

        // ---- online softmax (log2 domain; rows r, r+8; cols 8nt+2t,+1) ----
        float rm0 = -1e30f, rm1 = -1e30f;
#pragma unroll
        for (int nt = 0; nt < 8; nt++) {
            rm0 = fmaxf(rm0, fmaxf(S[nt][0], S[nt][1]));
            rm1 = fmaxf(rm1, fmaxf(S[nt][2], S[nt][3]));
        }
        rm0 = fmaxf(rm0, __shfl_xor_sync(0xffffffffu, rm0, 1, 4));
        rm0 = fmaxf(rm0, __shfl_xor_sync(0xffffffffu, rm0, 2, 4));
        rm1 = fmaxf(rm1, __shfl_xor_sync(0xffffffffu, rm1, 1, 4));
        rm1 = fmaxf(rm1, __shfl_xor_sync(0xffffffffu, rm1, 2, 4));
        float mn0 = fmaxf(mx0, rm0), mn1 = fmaxf(mx1, rm1);
        float c0 = ex2f(mx0 - mn0), c1 = ex2f(mx1 - mn1);
        mx0 = mn0; mx1 = mn1;
        if (__any_sync(0xffffffffu, (c0 < 1.f) | (c1 < 1.f))) {
            l0 *= c0; l1 *= c1;
            ex0 *= c0; ey0 *= c0; ew0 *= c0;
            ex1 *= c1; ey1 *= c1; ew1 *= c1;
#pragma unroll
            for (int cg = 0; cg < 16; cg++) {
                OUT[cg][0] *= c0; OUT[cg][1] *= c0;
                OUT[cg][2] *= c1; OUT[cg][3] *= c1;
            }
        }
#pragma unroll
        for (int nt = 0; nt < 8; nt++) {
            int col = 8 * nt + 2 * t;
            float pa = ex2f(S[nt][0] - mn0);
            float pb = ex2f(S[nt][1] - mn0);
            float pc = ex2f(S[nt][2] - mn1);
            float pd = ex2f(S[nt][3] - mn1);
            S[nt][0] = pa; S[nt][1] = pb; S[nt][2] = pc; S[nt][3] = pd;
            float xa = xs[col], xb = xs[col + 1];
            float ya = ys[col], yb = ys[col + 1];
            float wa = ws[col], wb = ws[col + 1];
            l0 += pa + pb;  l1 += pc + pd;
            ex0 = fmaf(pa, xa, ex0); ex0 = fmaf(pb, xb, ex0);
            ex1 = fmaf(pc, xa, ex1); ex1 = fmaf(pd, xb, ex1);
            ey0 = fmaf(pa, ya, ey0); ey0 = fmaf(pb, yb, ey0);
            ey1 = fmaf(pc, ya, ey1); ey1 = fmaf(pd, yb, ey1);
            ew0 = fmaf(pa, wa, ew0); ew0 = fmaf(pb, wb, ew0);
            ew1 = fmaf(pc, wa, ew1); ew1 = fmaf(pd, wb, ew1);
        }

        // ---- GEMM2: OUT += P * V  (P straight from D-fragments; no smem) ----
#pragma unroll
        for (int j = 0; j < 2; j++) {
            uint32_t a0 = packh2(S[4*j][0],   S[4*j][1]);
            uint32_t a1 = packh2(S[4*j][2],   S[4*j][3]);
            uint32_t a2 = packh2(S[4*j+1][0], S[4*j+1][1]);
            uint32_t a3 = packh2(S[4*j+1][2], S[4*j+1][3]);
            uint32_t b0 = packh2(S[4*j+2][0], S[4*j+2][1]);
            uint32_t b1 = packh2(S[4*j+2][2], S[4*j+2][3]);
            uint32_t b2 = packh2(S[4*j+3][0], S[4*j+3][1]);
            uint32_t b3 = packh2(S[4*j+3][2], S[4*j+3][3]);
#pragma unroll
            for (int cg = 0; cg < 16; cg++) {
                uint4 v = Vs[(cg * 2 + j) * 32 + lane];
                mma16(OUT[cg], a0, a1, a2, a3, v.x, v.y);
                mma16(OUT[cg], b0, b1, b2, b3, v.z, v.w);
            }
        }
    }

    // ---- epilogue ----
    int nq0 = n0 + w * 16 + r;
    int nq1 = nq0 + 8;
    const float* st0 = g_st + ((size_t)p * NN + nq0) * CC;
    const float* st1 = g_st + ((size_t)p * NN + nq1) * CC;
    float ssq0 = 0.f, ssq1 = 0.f, dot0 = 0.f, dot1 = 0.f;
#pragma unroll
    for (int cg = 0; cg < 16; cg++) {
        int c = 8 * cg + 2 * t;
        float2 s0 = *(const float2*)(st0 + c);
        float2 s1 = *(const float2*)(st1 + c);
        float a = OUT[cg][0], b = OUT[cg][1];
        float d = OUT[cg][2], e = OUT[cg][3];
        ssq0 = fmaf(a, a, ssq0); ssq0 = fmaf(b, b, ssq0);
        ssq1 = fmaf(d, d, ssq1); ssq1 = fmaf(e, e, ssq1);
        dot0 = fmaf(a, s0.x, dot0); dot0 = fmaf(b, s0.y, dot0);
        dot1 = fmaf(d, s1.x, dot1); dot1 = fmaf(e, s1.y, dot1);
    }
#pragma unroll
    for (int off = 1; off <= 2; off <<= 1) {
        l0   += __shfl_xor_sync(0xffffffffu, l0, off, 4);
        l1   += __shfl_xor_sync(0xffffffffu, l1, off, 4);
        ex0  += __shfl_xor_sync(0xffffffffu, ex0, off, 4);
        ex1  += __shfl_xor_sync(0xffffffffu, ex1, off, 4);
        ey0  += __shfl_xor_sync(0xffffffffu, ey0, off, 4);
        ey1  += __shfl_xor_sync(0xffffffffu, ey1, off, 4);
        ew0  += __shfl_xor_sync(0xffffffffu, ew0, off, 4);
        ew1  += __shfl_xor_sync(0xffffffffu, ew1, off, 4);
        ssq0 += __shfl_xor_sync(0xffffffffu, ssq0, off, 4);
        ssq1 += __shfl_xor_sync(0xffffffffu, ssq1, off, 4);
        dot0 += __shfl_xor_sync(0xffffffffu, dot0, off, 4);
        dot1 += __shfl_xor_sync(0xffffffffu, dot1, off, 4);
    }
    float* out_c = out + (size_t)p * 2 * NN;
    float* out_w = out + (size_t)PAIRS * 2 * NN + (size_t)p * NN;
    const float* sweights = weights + (size_t)(2 * p) * NN;
    if (t == 0) {
        float linv = 1.f / l0;
        out_c[nq0]      = ex0 * linv;
        out_c[NN + nq0] = ey0 * linv;
        float score = dot0 / (fmaxf(sqrtf(ssq0), 1e-12f) * 128.f);
        out_w[nq0] = 0.5f * (score + 1.f) * sweights[nq0] * (ew0 * linv);
    } else if (t == 1) {
        float linv = 1.f / l1;
        out_c[nq1]      = ex1 * linv;
        out_c[NN + nq1] = ey1 * linv;
        float score = dot1 / (fmaxf(sqrtf(ssq1), 1e-12f) * 128.f);
        out_w[nq1] = 0.5f * (score + 1.f) * sweights[nq1] * (ew1 * linv);
    }
}

extern "C" void kernel_launch(void* const* d_in, const int* in_sizes, int n_in,
                              void* d_out, int out_size) {
    const float* coords  = (const float*)d_in[0];  // [16][2][4096]
    const float* weights = (const float*)d_in[1];  // [16][1][4096]
    const float* desc    = (const float*)d_in[2];  // [16][128][4096]
    float* out = (float*)d_out;

    cudaFuncSetAttribute(flash_mma,
                         cudaFuncAttributeMaxDynamicSharedMemorySize, SM_TOT);

    norm_kernel<<<(16 * NN) / 256, 256>>>(desc);
    packQ<<<2048, 256>>>(desc);
    packK<<<4096, 256>>>(desc);
    packV<<<2048, 256>>>(desc);
    dim3 grid(NN / TQ, PAIRS);
    flash_mma<<<grid, NTHR, SM_TOT>>>(coords, weights, out);
}

// round 17
// speedup vs baseline: 6.4398x; 1.0403x over previous
#include <cuda_runtime.h>
#include <cuda_fp16.h>
#include <math.h>
#include <stdint.h>

#define PAIRS 8
#define CC 128
#define NN 4096
#define TM 64
#define TQ 128
#define NTHR 256
// fold 100x temp and log2(e) into the normalization: each side x 10*sqrt(log2 e)
#define SCALEF 12.0112238f

// ---------------- gmem scratch (packed fp16 mma fragments) ----------------
__device__ uint4 g_qh[PAIRS*256*8*32];
__device__ uint4 g_ql[PAIRS*256*8*32];
__device__ uint4 g_khl[PAIRS*512*8*32];
__device__ uint4 g_vp[PAIRS*64*16*2*32];
__device__ float g_st[PAIRS*NN*CC];
__device__ float g_inv[16*NN];

__device__ __forceinline__ uint32_t packh2(float a, float b) {
    __half2 h = __floats2half2_rn(a, b);
    return *reinterpret_cast<uint32_t*>(&h);
}
__device__ __forceinline__ float hlo(float x) { return x - __half2float(__float2half_rn(x)); }
__device__ __forceinline__ float ex2f(float x) {
    float r; asm("ex2.approx.ftz.f32 %0, %1;" : "=f"(r) : "f"(x)); return r;
}
__device__ __forceinline__ void mma16(float* d, uint32_t a0, uint32_t a1,
                                      uint32_t a2, uint32_t a3,
                                      uint32_t b0, uint32_t b1) {
    asm volatile(
        "mma.sync.aligned.m16n8k16.row.col.f32.f16.f16.f32 "
        "{%0,%1,%2,%3},{%4,%5,%6,%7},{%8,%9},{%0,%1,%2,%3};"
        : "+f"(d[0]), "+f"(d[1]), "+f"(d[2]), "+f"(d[3])
        : "r"(a0), "r"(a1), "r"(a2), "r"(a3), "r"(b0), "r"(b1));
}
__device__ __forceinline__ uint32_t smem_u32(const void* p) {
    uint32_t a;
    asm("{ .reg .u64 t; cvta.to.shared.u64 t, %1; cvt.u32.u64 %0, t; }" : "=r"(a) : "l"(p));
    return a;
}
#define CP_ASYNC16(saddr, gptr) \
    asm volatile("cp.async.cg.shared.global [%0], [%1], 16;" :: "r"(saddr), "l"(gptr))
#define CP_COMMIT() asm volatile("cp.async.commit_group;" ::: "memory")
#define CP_WAIT1()  asm volatile("cp.async.wait_group 1;" ::: "memory")

// ---------------- prep: norms ----------------
__global__ void norm_kernel(const float* __restrict__ desc) {
    int idx = blockIdx.x * blockDim.x + threadIdx.x;   // 16*4096
    int b = idx >> 12, n = idx & (NN - 1);
    const float* col = desc + (size_t)b * CC * NN + n;
    float ss = 0.f;
#pragma unroll 8
    for (int c = 0; c < CC; c++) { float v = col[(size_t)c * NN]; ss = fmaf(v, v, ss); }
    g_inv[idx] = SCALEF / fmaxf(sqrtf(ss), 1e-12f);
}

// ---------------- prep: fused Q/K/V fragment packing ----------------
__global__ void pack_all(const float* __restrict__ desc) {
    int bx = blockIdx.x;
    int tid = threadIdx.x;
    if (bx < 2048) {
        // ---- Q fragments (fp16 hi/lo) + raw src transpose ----
        int gid = bx * 256 + tid;
        int lane = gid & 31, ks = (gid >> 5) & 7, g16 = (gid >> 8) & 255, p = gid >> 16;
        int r = lane >> 2, t = lane & 3;
        int n = g16 * 16 + r, c = ks * 16 + 2 * t;
        const float* src = desc + (size_t)(2 * p) * CC * NN;
        float i0 = g_inv[(2 * p) * NN + n], i1 = g_inv[(2 * p) * NN + n + 8];
        float x00 = src[(size_t)c * NN + n],       x01 = src[(size_t)(c+1) * NN + n];
        float x10 = src[(size_t)c * NN + n + 8],   x11 = src[(size_t)(c+1) * NN + n + 8];
        float x20 = src[(size_t)(c+8) * NN + n],   x21 = src[(size_t)(c+9) * NN + n];
        float x30 = src[(size_t)(c+8) * NN + n+8], x31 = src[(size_t)(c+9) * NN + n+8];
        float* st = g_st + (size_t)p * NN * CC;
        st[(size_t)n * CC + c]           = x00;  st[(size_t)n * CC + c + 1]       = x01;
        st[(size_t)(n+8) * CC + c]       = x10;  st[(size_t)(n+8) * CC + c + 1]   = x11;
        st[(size_t)n * CC + c + 8]       = x20;  st[(size_t)n * CC + c + 9]       = x21;
        st[(size_t)(n+8) * CC + c + 8]   = x30;  st[(size_t)(n+8) * CC + c + 9]   = x31;
        float q00 = x00*i0, q01 = x01*i0, q10 = x10*i1, q11 = x11*i1;
        float q20 = x20*i0, q21 = x21*i0, q30 = x30*i1, q31 = x31*i1;
        g_qh[gid] = make_uint4(packh2(q00,q01), packh2(q10,q11),
                               packh2(q20,q21), packh2(q30,q31));
        g_ql[gid] = make_uint4(packh2(hlo(q00),hlo(q01)), packh2(hlo(q10),hlo(q11)),
                               packh2(hlo(q20),hlo(q21)), packh2(hlo(q30),hlo(q31)));
    } else if (bx < 6144) {
        // ---- K fragments (fp16 hi+lo packed in one uint4) ----
        int gid = (bx - 2048) * 256 + tid;
        int lane = gid & 31, ks = (gid >> 5) & 7, g8 = (gid >> 8) & 511, p = gid >> 17;
        int r = lane >> 2, t = lane & 3;
        int m = g8 * 8 + r, c = ks * 16 + 2 * t;
        const float* src = desc + (size_t)(2 * p + 1) * CC * NN;
        float inv = g_inv[(2 * p + 1) * NN + m];
        float v0 = src[(size_t)c * NN + m] * inv;
        float v1 = src[(size_t)(c+1) * NN + m] * inv;
        float v2 = src[(size_t)(c+8) * NN + m] * inv;
        float v3 = src[(size_t)(c+9) * NN + m] * inv;
        g_khl[gid] = make_uint4(packh2(v0, v1), packh2(v2, v3),
                                packh2(hlo(v0), hlo(v1)), packh2(hlo(v2), hlo(v3)));
    } else {
        // ---- V fragments (fp16, kp-pairs packed) ----
        int gid = (bx - 6144) * 256 + tid;
        int lane = gid & 31, j = (gid >> 5) & 1, cg = (gid >> 6) & 15;
        int mt = (gid >> 10) & 63, p = gid >> 16;
        int r = lane >> 2, t = lane & 3;
        int ch = cg * 8 + r;
        int key0 = mt * 64 + (2 * j) * 16 + 2 * t;
        int key1 = key0 + 16;
        const float* src = desc + (size_t)(2 * p + 1) * CC * NN + (size_t)ch * NN;
        g_vp[gid] = make_uint4(packh2(src[key0], src[key0 + 1]),
                               packh2(src[key0 + 8], src[key0 + 9]),
                               packh2(src[key1], src[key1 + 1]),
                               packh2(src[key1 + 8], src[key1 + 9]));
    }
}

// ---------------- main flash kernel ----------------
#define SMO_QL  32768
#define SMO_KHL 65536
#define SMO_V   98304
#define SMO_XS  114688
#define SMO_YS  114944
#define SMO_WS  115200
#define SM_TOT  115456

__global__ void __launch_bounds__(NTHR, 2)
flash_mma(const float* __restrict__ coords,
          const float* __restrict__ weights,
          float* __restrict__ out)
{
    extern __shared__ char smraw[];
    uint4* QHs  = (uint4*)smraw;
    uint4* QLs  = (uint4*)(smraw + SMO_QL);
    uint4* KHLs = (uint4*)(smraw + SMO_KHL);
    uint4* Vs   = (uint4*)(smraw + SMO_V);
    float* xs   = (float*)(smraw + SMO_XS);
    float* ys   = (float*)(smraw + SMO_YS);
    float* ws   = (float*)(smraw + SMO_WS);
    uint32_t sb = smem_u32(smraw);

    int p  = blockIdx.y;
    int n0 = blockIdx.x * TQ;
    int tid = threadIdx.x;
    int w = tid >> 5, lane = tid & 31;
    int r = lane >> 2, t = lane & 3;

    const float* tcoords  = coords  + (size_t)(2 * p + 1) * 2 * NN;
    const float* tweights = weights + (size_t)(2 * p + 1) * NN;
    const uint4* khg_base = g_khl + ((size_t)p * 512) * 8 * 32;
    const uint4* vg_base  = g_vp  + ((size_t)p * 64) * 16 * 2 * 32;

    // this warp's Q fragments -> smem (reused over all 64 key tiles)
    {
        size_t base = ((size_t)(p * 256 + blockIdx.x * 8 + w)) * 8;
#pragma unroll
        for (int ks = 0; ks < 8; ks++) {
            QHs[(w * 8 + ks) * 32 + lane] = g_qh[(base + ks) * 32 + lane];
            QLs[(w * 8 + ks) * 32 + lane] = g_ql[(base + ks) * 32 + lane];
        }
    }

    // ---- prologue: stage K(0), V(0) as two cp.async groups ----
    {
        const uint4* khg = khg_base;
#pragma unroll
        for (int i = 0; i < 8; i++) {
            int idx = i * 256 + tid;
            CP_ASYNC16(sb + SMO_KHL + idx * 16, khg + idx);
        }
        CP_COMMIT();
        const uint4* vg = vg_base;
#pragma unroll
        for (int i = 0; i < 4; i++) {
            int idx = i * 256 + tid;
            CP_ASYNC16(sb + SMO_V + idx * 16, vg + idx);
        }
        CP_COMMIT();
    }

    float OUT[16][4];
#pragma unroll
    for (int cg = 0; cg < 16; cg++)
#pragma unroll
        for (int k = 0; k < 4; k++) OUT[cg][k] = 0.f;

    float mx0 = -1e30f, mx1 = -1e30f;
    float l0 = 0.f, l1 = 0.f;
    float ex0 = 0.f, ex1 = 0.f, ey0 = 0.f, ey1 = 0.f, ew0 = 0.f, ew1 = 0.f;

    for (int mt = 0; mt < 64; mt++) {
        int m0 = mt * TM;
        int nxt = (mt + 1) & 63;

        // ---- K(mt) ready (V(mt) may still be in flight) ----
        CP_WAIT1();
        __syncthreads();

        // coords for THIS tile (read in softmax, after the post-GEMM1 barrier)
        if (tid < 64)       xs[tid]       = tcoords[m0 + tid];
        else if (tid < 128) ys[tid - 64]  = tcoords[NN + m0 + tid - 64];
        else if (tid < 192) ws[tid - 128] = tweights[m0 + tid - 128];

        // ---- GEMM1: S = Qh*Kh + Ql*Kh + Qh*Kl (logits in log2 domain) ----
        float S[8][4];
#pragma unroll
        for (int nt = 0; nt < 8; nt++)
#pragma unroll
            for (int k = 0; k < 4; k++) S[nt][k] = 0.f;

#pragma unroll
        for (int ks = 0; ks < 8; ks++) {
            uint4 qh = QHs[(w * 8 + ks) * 32 + lane];
            uint4 ql = QLs[(w * 8 + ks) * 32 + lane];
#pragma unroll
            for (int nt = 0; nt < 8; nt++) {
                uint4 k4 = KHLs[(nt * 8 + ks) * 32 + lane];
                mma16(S[nt], qh.x, qh.y, qh.z, qh.w, k4.x, k4.y);
                mma16(S[nt], ql.x, ql.y, ql.z, ql.w, k4.x, k4.y);
                mma16(S[nt], qh.x, qh.y, qh.z, qh.w, k4.z, k4.w);
            }
        }
        __syncthreads();   // all warps done reading KHL

        // ---- prefetch K(mt+1) in place (hidden under softmax + GEMM2) ----
        {
            const uint4* khg = khg_base + ((size_t)nxt * 8) * 8 * 32;
#pragma unroll
            for (int i = 0; i < 8; i++) {
                int idx = i * 256 + tid;
                CP_ASYNC16(sb + SMO_KHL + idx * 16, khg + idx);
            }
            CP_COMMIT();
        }

        // ---- online softmax (log2 domain; rows r, r+8; cols 8nt+2t,+1) ----
        float rm0 = -1e30f, rm1 = -1e30f;
#pragma unroll
        for (int nt = 0; nt < 8; nt++) {
            rm0 = fmaxf(rm0, fmaxf(S[nt][0], S[nt][1]));
            rm1 = fmaxf(rm1, fmaxf(S[nt][2], S[nt][3]));
        }
        rm0 = fmaxf(rm0, __shfl_xor_sync(0xffffffffu, rm0, 1, 4));
        rm0 = fmaxf(rm0, __shfl_xor_sync(0xffffffffu, rm0, 2, 4));
        rm1 = fmaxf(rm1, __shfl_xor_sync(0xffffffffu, rm1, 1, 4));
        rm1 = fmaxf(rm1, __shfl_xor_sync(0xffffffffu, rm1, 2, 4));
        float mn0 = fmaxf(mx0, rm0), mn1 = fmaxf(mx1, rm1);
        float c0 = ex2f(mx0 - mn0), c1 = ex2f(mx1 - mn1);
        mx0 = mn0; mx1 = mn1;
        if (__any_sync(0xffffffffu, (c0 < 1.f) | (c1 < 1.f))) {
            l0 *= c0; l1 *= c1;
            ex0 *= c0; ey0 *= c0; ew0 *= c0;
            ex1 *= c1; ey1 *= c1; ew1 *= c1;
#pragma unroll
            for (int cg = 0; cg < 16; cg++) {
                OUT[cg][0] *= c0; OUT[cg][1] *= c0;
                OUT[cg][2] *= c1; OUT[cg][3] *= c1;
            }
        }
#pragma unroll
        for (int nt = 0; nt < 8; nt++) {
            int col = 8 * nt + 2 * t;
            float pa = ex2f(S[nt][0] - mn0);
            float pb = ex2f(S[nt][1] - mn0);
            float pc = ex2f(S[nt][2] - mn1);
            float pd = ex2f(S[nt][3] - mn1);
            S[nt][0] = pa; S[nt][1] = pb; S[nt][2] = pc; S[nt][3] = pd;
            float xa = xs[col], xb = xs[col + 1];
            float ya = ys[col], yb = ys[col + 1];
            float wa = ws[col], wb = ws[col + 1];
            l0 += pa + pb;  l1 += pc + pd;
            ex0 = fmaf(pa, xa, ex0); ex0 = fmaf(pb, xb, ex0);
            ex1 = fmaf(pc, xa, ex1); ex1 = fmaf(pd, xb, ex1);
            ey0 = fmaf(pa, ya, ey0); ey0 = fmaf(pb, yb, ey0);
            ey1 = fmaf(pc, ya, ey1); ey1 = fmaf(pd, yb, ey1);
            ew0 = fmaf(pa, wa, ew0); ew0 = fmaf(pb, wb, ew0);
            ew1 = fmaf(pc, wa, ew1); ew1 = fmaf(pd, wb, ew1);
        }

        // ---- V(mt) ready (K(mt+1) may still be in flight) ----
        CP_WAIT1();
        __syncthreads();

        // ---- GEMM2: OUT += P * V  (P straight from D-fragments) ----
#pragma unroll
        for (int j = 0; j < 2; j++) {
            uint32_t a0 = packh2(S[4*j][0],   S[4*j][1]);
            uint32_t a1 = packh2(S[4*j][2],   S[4*j][3]);
            uint32_t a2 = packh2(S[4*j+1][0], S[4*j+1][1]);
            uint32_t a3 = packh2(S[4*j+1][2], S[4*j+1][3]);
            uint32_t b0 = packh2(S[4*j+2][0], S[4*j+2][1]);
            uint32_t b1 = packh2(S[4*j+2][2], S[4*j+2][3]);
            uint32_t b2 = packh2(S[4*j+3][0], S[4*j+3][1]);
            uint32_t b3 = packh2(S[4*j+3][2], S[4*j+3][3]);
#pragma unroll
            for (int cg = 0; cg < 16; cg++) {
                uint4 v = Vs[(cg * 2 + j) * 32 + lane];
                mma16(OUT[cg], a0, a1, a2, a3, v.x, v.y);
                mma16(OUT[cg], b0, b1, b2, b3, v.z, v.w);
            }
        }
        __syncthreads();   // all warps done reading Vs

        // ---- prefetch V(mt+1) in place (hidden under next GEMM1 + softmax) ----
        {
            const uint4* vg = vg_base + ((size_t)nxt) * 16 * 2 * 32;
#pragma unroll
            for (int i = 0; i < 4; i++) {
                int idx = i * 256 + tid;
                CP_ASYNC16(sb + SMO_V + idx * 16, vg + idx);
            }
            CP_COMMIT();
        }
    }

    // ---- epilogue ----
    int nq0 = n0 + w * 16 + r;
    int nq1 = nq0 + 8;
    const float* st0 = g_st + ((size_t)p * NN + nq0) * CC;
    const float* st1 = g_st + ((size_t)p * NN + nq1) * CC;
    float ssq0 = 0.f, ssq1 = 0.f, dot0 = 0.f, dot1 = 0.f;
#pragma unroll
    for (int cg = 0; cg < 16; cg++) {
        int c = 8 * cg + 2 * t;
        float2 s0 = *(const float2*)(st0 + c);
        float2 s1 = *(const float2*)(st1 + c);
        float a = OUT[cg][0], b = OUT[cg][1];
        float d = OUT[cg][2], e = OUT[cg][3];
        ssq0 = fmaf(a, a, ssq0); ssq0 = fmaf(b, b, ssq0);
        ssq1 = fmaf(d, d, ssq1); ssq1 = fmaf(e, e, ssq1);
        dot0 = fmaf(a, s0.x, dot0); dot0 = fmaf(b, s0.y, dot0);
        dot1 = fmaf(d, s1.x, dot1); dot1 = fmaf(e, s1.y, dot1);
    }
#pragma unroll
    for (int off = 1; off <= 2; off <<= 1) {
        l0   += __shfl_xor_sync(0xffffffffu, l0, off, 4);
        l1   += __shfl_xor_sync(0xffffffffu, l1, off, 4);
        ex0  += __shfl_xor_sync(0xffffffffu, ex0, off, 4);
        ex1  += __shfl_xor_sync(0xffffffffu, ex1, off, 4);
        ey0  += __shfl_xor_sync(0xffffffffu, ey0, off, 4);
        ey1  += __shfl_xor_sync(0xffffffffu, ey1, off, 4);
        ew0  += __shfl_xor_sync(0xffffffffu, ew0, off, 4);
        ew1  += __shfl_xor_sync(0xffffffffu, ew1, off, 4);
        ssq0 += __shfl_xor_sync(0xffffffffu, ssq0, off, 4);
        ssq1 += __shfl_xor_sync(0xffffffffu, ssq1, off, 4);
        dot0 += __shfl_xor_sync(0xffffffffu, dot0, off, 4);
        dot1 += __shfl_xor_sync(0xffffffffu, dot1, off, 4);
    }
    float* out_c = out + (size_t)p * 2 * NN;
    float* out_w = out + (size_t)PAIRS * 2 * NN + (size_t)p * NN;
    const float* sweights = weights + (size_t)(2 * p) * NN;
    if (t == 0) {
        float linv = 1.f / l0;
        out_c[nq0]      = ex0 * linv;
        out_c[NN + nq0] = ey0 * linv;
        float score = dot0 / (fmaxf(sqrtf(ssq0), 1e-12f) * 128.f);
        out_w[nq0] = 0.5f * (score + 1.f) * sweights[nq0] * (ew0 * linv);
    } else if (t == 1) {
        float linv = 1.f / l1;
        out_c[nq1]      = ex1 * linv;
        out_c[NN + nq1] = ey1 * linv;
        float score = dot1 / (fmaxf(sqrtf(ssq1), 1e-12f) * 128.f);
        out_w[nq1] = 0.5f * (score + 1.f) * sweights[nq1] * (ew1 * linv);
    }
}

extern "C" void kernel_launch(void* const* d_in, const int* in_sizes, int n_in,
                              void* d_out, int out_size) {
    const float* coords  = (const float*)d_in[0];  // [16][2][4096]
    const float* weights = (const float*)d_in[1];  // [16][1][4096]
    const float* desc    = (const float*)d_in[2];  // [16][128][4096]
    float* out = (float*)d_out;

    cudaFuncSetAttribute(flash_mma,
                         cudaFuncAttributeMaxDynamicSharedMemorySize, SM_TOT);

    norm_kernel<<<(16 * NN) / 256, 256>>>(desc);
    pack_all<<<8192, 256>>>(desc);
    dim3 grid(NN / TQ, PAIRS);
    flash_mma<<<grid, NTHR, SM_TOT>>>(coords, weights, out);
}